// round 9
// baseline (speedup 1.0000x reference)
#include <cuda_runtime.h>
#include <cstdio>
#include <cstdlib>
#include <math.h>

#define NN 100000
#define NE 1600000
#define HIDD 64
#define NEGS 0.2f
#define NEGINF (-1e30f)
#define SCB 128   // scan blocks (128*256*4 = 131072 >= NN)

// ---------------- scratch (device globals; zero-init at load) --------------
__device__ __align__(16) int   d_cnt[NN];
__device__ __align__(16) int   d_rs[NN + 1];
__device__ __align__(16) int   d_cur[NN];
__device__ __align__(16) int   d_part[SCB];
__device__ __align__(16) int   d_pbase[SCB];
__device__ __align__(16) int   d_ssrc[NE];
__device__ __align__(16) int   d_sdst[NE];
__device__ __align__(16) int   d_seid[NE];
__device__ __align__(16) float d_asort[NE];
__device__ __align__(16) float d_h2[NN * HIDD];
__device__ __align__(16) float d_als2[NN];
__device__ __align__(16) float d_ald2[NN];
__device__ __align__(16) float d_gv[NN * HIDD];
// folded layer-1 constants
__device__ __align__(16) float d_u0[4], d_u1[4];   // as1 dots:  als1 = x0*u0+x1*u1
__device__ __align__(16) float d_v0[4], d_v1[4];   // ad1 dots
__device__ __align__(16) float d_c1[4];            // attr coeff per head (L1)
__device__ float d_c2s;                            // attr coeff (L2)
__device__ __align__(16) float d_G[512];           // [i][h][j] = W1(i,h,:)@W2(h,:,j)
__device__ __align__(16) float d_bvec[64];         // b1 @ W2

__device__ __forceinline__ float lrelu(float x) { return x > 0.f ? x : NEGS * x; }

__device__ __forceinline__ void mzmerge(float& m, float& z, float om, float oz) {
    float nm = fmaxf(m, om);
    float ea = (m == nm) ? 1.f : __expf(m - nm);
    float eb = (om == nm) ? 1.f : __expf(om - nm);
    z = z * ea + oz * eb;
    m = nm;
}
__device__ __forceinline__ void mzupd(float& m, float& z, float l) {
    float nm = fmaxf(m, l);
    z = z * __expf(m - nm) + __expf(l - nm);
    m = nm;
}

// ---------------- CSR build ----------------
__global__ void __launch_bounds__(256) k_zero() {
    int i = blockIdx.x * 256 + threadIdx.x;
    if (i < NN) d_cnt[i] = 0;
}

__global__ void __launch_bounds__(256) k_count(const int* __restrict__ ei) {
    int e = blockIdx.x * 256 + threadIdx.x;
    if (e < NE) {
        int d = ei[NE + e];
        if ((unsigned)d < NN) atomicAdd(&d_cnt[d], 1);
    }
}

// helper: sum of this thread's 4-count chunk
__device__ __forceinline__ int scan_chunk_sum(int i0) {
    int s = 0;
#pragma unroll
    for (int j = 0; j < 4; j++) {
        int i = i0 + j;
        if (i < NN) s += d_cnt[i];
    }
    return s;
}

// phase 1: per-block sums
__global__ void __launch_bounds__(256) k_scan1() {
    __shared__ int sh[256];
    int t = threadIdx.x;
    int i0 = blockIdx.x * 1024 + t * 4;
    sh[t] = scan_chunk_sum(i0);
    __syncthreads();
    for (int off = 128; off; off >>= 1) {
        if (t < off) sh[t] += sh[t + off];
        __syncthreads();
    }
    if (t == 0) d_part[blockIdx.x] = sh[0];
}

// phase 2: scan the 128 partials (1 block)
__global__ void __launch_bounds__(SCB) k_scan2() {
    __shared__ int sh[SCB];
    int t = threadIdx.x;
    int v = d_part[t];
    sh[t] = v;
    __syncthreads();
    for (int off = 1; off < SCB; off <<= 1) {
        int u = (t >= off) ? sh[t - off] : 0;
        __syncthreads();
        sh[t] += u;
        __syncthreads();
    }
    d_pbase[t] = sh[t] - v;  // exclusive base per block
    if (t == SCB - 1) d_rs[NN] = sh[SCB - 1];
}

// phase 3: full prefix write
__global__ void __launch_bounds__(256) k_scan3() {
    __shared__ int sh[256];
    int t = threadIdx.x;
    int i0 = blockIdx.x * 1024 + t * 4;
    int s = scan_chunk_sum(i0);
    sh[t] = s;
    __syncthreads();
    for (int off = 1; off < 256; off <<= 1) {
        int u = (t >= off) ? sh[t - off] : 0;
        __syncthreads();
        sh[t] += u;
        __syncthreads();
    }
    int run = d_pbase[blockIdx.x] + sh[t] - s;
#pragma unroll
    for (int j = 0; j < 4; j++) {
        int i = i0 + j;
        if (i < NN) {
            d_rs[i] = run;
            d_cur[i] = run;
            run += d_cnt[i];
        }
    }
}

// ---------------- precompute folded constants ----------------
__global__ void __launch_bounds__(256) k_pre(const float* __restrict__ W1,
                                             const float* __restrict__ as1,
                                             const float* __restrict__ ad1,
                                             const float* __restrict__ We1,
                                             const float* __restrict__ ae1,
                                             const float* __restrict__ We2,
                                             const float* __restrict__ ae2,
                                             const float* __restrict__ b1,
                                             const float* __restrict__ W2) {
    int t = threadIdx.x;
    if (t < 4) {
        float s = 0;
        for (int d = 0; d < 64; d++) s += W1[t * 64 + d] * as1[t * 64 + d];
        d_u0[t] = s;
    } else if (t < 8) {
        int h = t - 4;
        float s = 0;
        for (int d = 0; d < 64; d++) s += W1[256 + h * 64 + d] * as1[h * 64 + d];
        d_u1[h] = s;
    } else if (t < 12) {
        int h = t - 8;
        float s = 0;
        for (int d = 0; d < 64; d++) s += W1[h * 64 + d] * ad1[h * 64 + d];
        d_v0[h] = s;
    } else if (t < 16) {
        int h = t - 12;
        float s = 0;
        for (int d = 0; d < 64; d++) s += W1[256 + h * 64 + d] * ad1[h * 64 + d];
        d_v1[h] = s;
    } else if (t < 20) {
        int h = t - 16;
        float s = 0;
        for (int d = 0; d < 64; d++) s += We1[h * 64 + d] * ae1[h * 64 + d];
        d_c1[h] = s;
    } else if (t == 20) {
        float s = 0;
        for (int d = 0; d < 64; d++) s += We2[d] * ae2[d];
        d_c2s = s;
    }
    if (t >= 64 && t < 128) {
        int j = t - 64;
        float s = 0;
        for (int c = 0; c < 256; c++) s += b1[c] * W2[c * 64 + j];
        d_bvec[j] = s;
    }
#pragma unroll
    for (int rep = 0; rep < 2; rep++) {
        int idx = rep * 256 + t;
        int i = idx >> 8, rem = idx & 255, h = rem >> 6, j = rem & 63;
        float s = 0;
        for (int d = 0; d < 64; d++)
            s += W1[i * 256 + h * 64 + d] * W2[(h * 64 + d) * 64 + j];
        d_G[idx] = s;
    }
}

// ---------------- fill CSR buckets (sorted src/dst/eid/attr) ----------------
__global__ void __launch_bounds__(256) k_fill(const int* __restrict__ ei,
                                              const float* __restrict__ attr) {
    int e = blockIdx.x * 256 + threadIdx.x;
    if (e >= NE) return;
    int s = ei[e], dd = ei[NE + e];
    if ((unsigned)s >= NN || (unsigned)dd >= NN) return;
    int pos = atomicAdd(&d_cur[dd], 1);
    if ((unsigned)pos >= NE) return;
    d_ssrc[pos] = s;
    d_sdst[pos] = dd;
    d_seid[pos] = e;
    d_asort[pos] = attr[e];
}

// ---------------- layer-1 fused: softmax + rank-2 agg + @W2 + dots ---------
__global__ void __launch_bounds__(256) k_agg1(const float* __restrict__ x,
                                              const float* __restrict__ as2,
                                              const float* __restrict__ ad2) {
    int warp = threadIdx.x >> 5, lane = threadIdx.x & 31;
    int n = blockIdx.x * 8 + warp;   // grid exact: n < NN always
    int r0 = d_rs[n], r1 = d_rs[n + 1];

    float2 xn = __ldg((const float2*)x + n);
    float adh[4], u0[4], u1[4], c1[4];
#pragma unroll
    for (int h = 0; h < 4; h++) {
        u0[h] = d_u0[h]; u1[h] = d_u1[h]; c1[h] = d_c1[h];
        adh[h] = xn.x * d_v0[h] + xn.y * d_v1[h];
    }

    float m[4] = {NEGINF, NEGINF, NEGINF, NEGINF};
    float z[4] = {0, 0, 0, 0};
    for (int pos = r0 + lane; pos < r1; pos += 32) {
        int s = __ldg(&d_ssrc[pos]);
        float a = __ldg(&d_asort[pos]);
        float2 xs = __ldg((const float2*)x + s);
#pragma unroll
        for (int h = 0; h < 4; h++) {
            float lg = lrelu(xs.x * u0[h] + xs.y * u1[h] + adh[h] + a * c1[h]);
            mzupd(m[h], z[h], lg);
        }
    }
#pragma unroll
    for (int off = 16; off; off >>= 1) {
#pragma unroll
        for (int h = 0; h < 4; h++) {
            float om = __shfl_xor_sync(0xffffffffu, m[h], off);
            float oz = __shfl_xor_sync(0xffffffffu, z[h], off);
            mzmerge(m[h], z[h], om, oz);
        }
    }
    float rz[4];
#pragma unroll
    for (int h = 0; h < 4; h++) rz[h] = 1.f / (z[h] + 1e-16f);

    float acc[8] = {0, 0, 0, 0, 0, 0, 0, 0};
    for (int pos = r0 + lane; pos < r1; pos += 32) {
        int s = __ldg(&d_ssrc[pos]);
        float a = __ldg(&d_asort[pos]);
        float2 xs = __ldg((const float2*)x + s);
#pragma unroll
        for (int h = 0; h < 4; h++) {
            float lg = lrelu(xs.x * u0[h] + xs.y * u1[h] + adh[h] + a * c1[h]);
            float al = __expf(lg - m[h]) * rz[h];
            acc[2 * h] += al * xs.x;
            acc[2 * h + 1] += al * xs.y;
        }
    }
#pragma unroll
    for (int off = 16; off; off >>= 1)
#pragma unroll
        for (int q = 0; q < 8; q++)
            acc[q] += __shfl_xor_sync(0xffffffffu, acc[q], off);

    int j0 = 2 * lane;
    float h0 = __ldg(&d_bvec[j0]), h1v = __ldg(&d_bvec[j0 + 1]);
#pragma unroll
    for (int h = 0; h < 4; h++) {
#pragma unroll
        for (int i = 0; i < 2; i++) {
            float2 g = *(const float2*)(d_G + (i * 4 + h) * 64 + j0);
            float sv = acc[2 * h + i];
            h0 += sv * g.x;
            h1v += sv * g.y;
        }
    }
    *(float2*)(d_h2 + (long)n * 64 + j0) = make_float2(h0, h1v);

    float2 a2 = __ldg((const float2*)as2 + lane);
    float2 dd2 = __ldg((const float2*)ad2 + lane);
    float pa = h0 * a2.x + h1v * a2.y;
    float pd = h0 * dd2.x + h1v * dd2.y;
#pragma unroll
    for (int off = 16; off; off >>= 1) {
        pa += __shfl_xor_sync(0xffffffffu, pa, off);
        pd += __shfl_xor_sync(0xffffffffu, pd, off);
    }
    if (lane == 0) {
        d_als2[n] = pa;
        d_ald2[n] = pd;
    }
}

// ---------------- layer-2 softmax + agg + fused @Wr1 epilogue --------------
__global__ void __launch_bounds__(256) k_agg2(const float* __restrict__ b2,
                                              const float* __restrict__ Wr1) {
    __shared__ float shW[64 * 64];   // Wr1 row-major [k][j]
    __shared__ float shRow[8][64];
    int t = threadIdx.x;
    for (int idx = t; idx < 4096; idx += 256) shW[idx] = Wr1[idx];
    __syncthreads();

    int warp = t >> 5, lane = t & 31;
    int n = blockIdx.x * 8 + warp;   // grid exact
    int r0 = d_rs[n], r1 = d_rs[n + 1];
    float aldn = d_ald2[n];
    float c2 = d_c2s;

    float m = NEGINF, z = 0.f;
    for (int pos = r0 + lane; pos < r1; pos += 32) {
        int s = __ldg(&d_ssrc[pos]);
        float a = __ldg(&d_asort[pos]);
        mzupd(m, z, lrelu(__ldg(&d_als2[s]) + aldn + a * c2));
    }
#pragma unroll
    for (int off = 16; off; off >>= 1) {
        float om = __shfl_xor_sync(0xffffffffu, m, off);
        float oz = __shfl_xor_sync(0xffffffffu, z, off);
        mzmerge(m, z, om, oz);
    }
    float rz = 1.f / (z + 1e-16f);

    float a0 = 0.f, a1 = 0.f;
    int c0 = lane * 2;
    for (int pos = r0; pos < r1; pos++) {
        int s = __ldg(&d_ssrc[pos]);
        float a = __ldg(&d_asort[pos]);
        float lg = lrelu(__ldg(&d_als2[s]) + aldn + a * c2);
        float al = __expf(lg - m) * rz;
        float2 v = *(const float2*)(d_h2 + (long)s * 64 + c0);
        a0 += al * v.x;
        a1 += al * v.y;
    }
    float2 bb = __ldg((const float2*)(b2 + c0));
    float r0v = a0 + bb.x, r1v = a1 + bb.y;   // out2[n][c0], [c0+1]

    // fused gv[n] = out2[n] @ Wr1
    shRow[warp][c0] = r0v;
    shRow[warp][c0 + 1] = r1v;
    __syncwarp();
    float g0 = 0.f, g1 = 0.f;
#pragma unroll 16
    for (int k = 0; k < 64; k++) {
        float a = shRow[warp][k];
        float2 w = *(const float2*)(shW + k * 64 + c0);
        g0 += a * w.x;
        g1 += a * w.y;
    }
    *(float2*)(d_gv + (long)n * 64 + c0) = make_float2(g0, g1);
}

// ---------------- final edge regressor (CSR order; 8 lanes per edge) -------
__global__ void __launch_bounds__(256) k_edge(const float* __restrict__ br1,
                                              const float* __restrict__ Wr2,
                                              const float* __restrict__ br2,
                                              float* __restrict__ out) {
    int t = blockIdx.x * 256 + threadIdx.x;
    int pos = t >> 3;
    if (pos >= NE) return;
    int o = t & 7;
    int s = __ldg(&d_ssrc[pos]), dd = __ldg(&d_sdst[pos]);
    int c0 = o * 8;
    const float4* gs = (const float4*)(d_gv + (long)s * 64 + c0);
    const float4* gd = (const float4*)(d_gv + (long)dd * 64 + c0);
    float4 s0 = __ldg(gs), s1 = __ldg(gs + 1);
    float4 t0 = __ldg(gd), t1 = __ldg(gd + 1);
    float4 w0 = __ldg((const float4*)(Wr2 + c0)), w1 = __ldg((const float4*)(Wr2 + c0 + 4));
    float4 r0 = __ldg((const float4*)(br1 + c0)), r1 = __ldg((const float4*)(br1 + c0 + 4));
    float p = 0.f;
    p += fmaxf(s0.x + t0.x + r0.x, 0.f) * w0.x;
    p += fmaxf(s0.y + t0.y + r0.y, 0.f) * w0.y;
    p += fmaxf(s0.z + t0.z + r0.z, 0.f) * w0.z;
    p += fmaxf(s0.w + t0.w + r0.w, 0.f) * w0.w;
    p += fmaxf(s1.x + t1.x + r1.x, 0.f) * w1.x;
    p += fmaxf(s1.y + t1.y + r1.y, 0.f) * w1.y;
    p += fmaxf(s1.z + t1.z + r1.z, 0.f) * w1.z;
    p += fmaxf(s1.w + t1.w + r1.w, 0.f) * w1.w;
#pragma unroll
    for (int off = 4; off; off >>= 1) p += __shfl_down_sync(0xffffffffu, p, off);
    if (o == 0) out[__ldg(&d_seid[pos])] = p + __ldg(br2);
}

// ---------------- host diagnostics (static; no allocation) -----------------
static int   h_rs[1];
static float h_h2[2], h_gv[2], h_out[8];

// ---------------- launch ----------------
extern "C" void kernel_launch(void* const* d_in, const int* in_sizes, int n_in,
                              void* d_out, int out_size) {
    const float* x    = (const float*)d_in[0];
    const int*   ei   = (const int*)d_in[1];
    const float* attr = (const float*)d_in[2];
    const float* W1   = (const float*)d_in[3];
    const float* We1  = (const float*)d_in[4];
    const float* as1  = (const float*)d_in[5];
    const float* ad1  = (const float*)d_in[6];
    const float* ae1  = (const float*)d_in[7];
    const float* b1   = (const float*)d_in[8];
    const float* W2   = (const float*)d_in[9];
    const float* We2  = (const float*)d_in[10];
    const float* as2  = (const float*)d_in[11];
    const float* ad2  = (const float*)d_in[12];
    const float* ae2  = (const float*)d_in[13];
    const float* b2   = (const float*)d_in[14];
    const float* Wr1  = (const float*)d_in[15];
    const float* br1  = (const float*)d_in[16];
    const float* Wr2  = (const float*)d_in[17];
    const float* br2  = (const float*)d_in[18];
    float* out = (float*)d_out;

    const int EB = (NE + 255) / 256;
    const int NB8 = (NN + 7) / 8;     // 12500 (exact: 12500*8 == NN)
    const int ZB = (NN + 255) / 256;

    k_zero<<<ZB, 256>>>();
    k_count<<<EB, 256>>>(ei);
    k_pre<<<1, 256>>>(W1, as1, ad1, We1, ae1, We2, ae2, b1, W2);
    k_scan1<<<SCB, 256>>>();
    k_scan2<<<1, SCB>>>();
    k_scan3<<<SCB, 256>>>();
    k_fill<<<EB, 256>>>(ei, attr);
    k_agg1<<<NB8, 256>>>(x, as2, ad2);
    k_agg2<<<NB8, 256>>>(b2, Wr1);
    k_edge<<<(NE * 8 + 255) / 256, 256>>>(br1, Wr2, br2, out);

    // -------- slim health check: only on the non-capture correctness call --
    cudaStreamCaptureStatus cs = cudaStreamCaptureStatusNone;
    cudaStreamIsCapturing((cudaStream_t)0, &cs);
    if (cs != cudaStreamCaptureStatusNone) return;

    h_rs[0] = -777;
    cudaMemcpyFromSymbolAsync(h_rs, d_rs, 4, (size_t)NN * 4, cudaMemcpyDeviceToHost, 0);
    cudaMemcpyFromSymbolAsync(h_h2, d_h2, 8, 0, cudaMemcpyDeviceToHost, 0);
    cudaMemcpyFromSymbolAsync(h_gv, d_gv, 8, 0, cudaMemcpyDeviceToHost, 0);
    cudaMemcpyAsync(h_out, out, 32, cudaMemcpyDeviceToHost, 0);
    cudaError_t sticky = cudaGetLastError();

    float omax = 0.f;
    bool ofin = true;
    for (int i = 0; i < 8; i++) {
        if (!isfinite(h_out[i])) ofin = false;
        float a = fabsf(h_out[i]);
        if (a > omax) omax = a;
    }
    bool healthy = sticky == cudaSuccess && h_rs[0] == NE && ofin &&
                   omax > 1e-30f &&
                   (fabsf(h_h2[0]) + fabsf(h_h2[1])) > 0.f &&
                   (fabsf(h_gv[0]) + fabsf(h_gv[1])) > 0.f;
    if (healthy) return;

    for (int pass = 0; pass < 2; pass++) {
        FILE* f = pass ? stderr : stdout;
        fprintf(f, "DG sticky=%d(%s) rsN=%d h2=[%g %g] gv=[%g %g] out=[%g %g %g %g]\n",
                (int)sticky, cudaGetErrorString(sticky), h_rs[0],
                h_h2[0], h_h2[1], h_gv[0], h_gv[1],
                h_out[0], h_out[1], h_out[2], h_out[3]);
        fflush(f);
    }
    abort();
}

// round 10
// speedup vs baseline: 1.3182x; 1.3182x over previous
#include <cuda_runtime.h>
#include <cstdio>
#include <cstdlib>
#include <math.h>

#define NN 100000
#define NE 1600000
#define HIDD 64
#define NEGS 0.2f
#define SCB 128   // scan blocks (128*256*4 = 131072 >= NN)

// ---------------- scratch (device globals; zero-init at load) --------------
__device__ __align__(16) int   d_cnt[NN];
__device__ __align__(16) int   d_rs[NN + 1];
__device__ __align__(16) int   d_cur[NN];
__device__ __align__(16) int   d_part[SCB];
__device__ __align__(16) int   d_pbase[SCB];
__device__ __align__(16) int4  d_pack[NE];        // {src, dst, eid, attr-bits}
__device__ __align__(16) float d_h2[NN * HIDD];
__device__ __align__(16) float d_als2[NN];
__device__ __align__(16) float d_ald2[NN];
__device__ __align__(16) float d_out2[NN * HIDD];
__device__ __align__(16) float d_gv[NN * HIDD];
// folded layer-1 constants
__device__ __align__(16) float d_u0[4], d_u1[4];   // as1 dots:  als1 = x0*u0+x1*u1
__device__ __align__(16) float d_v0[4], d_v1[4];   // ad1 dots
__device__ __align__(16) float d_c1[4];            // attr coeff per head (L1)
__device__ float d_c2s;                            // attr coeff (L2)
__device__ __align__(16) float d_G[512];           // [i][h][j] = W1(i,h,:)@W2(h,:,j)
__device__ __align__(16) float d_bvec[64];         // b1 @ W2

__device__ __forceinline__ float lrelu(float x) { return x > 0.f ? x : NEGS * x; }

// ---------------- CSR build ----------------
__global__ void __launch_bounds__(256) k_zero() {
    int i = blockIdx.x * 256 + threadIdx.x;
    if (i < NN) d_cnt[i] = 0;
}

__global__ void __launch_bounds__(256) k_count(const int* __restrict__ ei) {
    int e = blockIdx.x * 256 + threadIdx.x;
    if (e < NE) {
        int d = ei[NE + e];
        if ((unsigned)d < NN) atomicAdd(&d_cnt[d], 1);
    }
}

__device__ __forceinline__ int scan_chunk_sum(int i0) {
    int s = 0;
#pragma unroll
    for (int j = 0; j < 4; j++) {
        int i = i0 + j;
        if (i < NN) s += d_cnt[i];
    }
    return s;
}

__global__ void __launch_bounds__(256) k_scan1() {
    __shared__ int sh[256];
    int t = threadIdx.x;
    int i0 = blockIdx.x * 1024 + t * 4;
    sh[t] = scan_chunk_sum(i0);
    __syncthreads();
    for (int off = 128; off; off >>= 1) {
        if (t < off) sh[t] += sh[t + off];
        __syncthreads();
    }
    if (t == 0) d_part[blockIdx.x] = sh[0];
}

__global__ void __launch_bounds__(SCB) k_scan2() {
    __shared__ int sh[SCB];
    int t = threadIdx.x;
    int v = d_part[t];
    sh[t] = v;
    __syncthreads();
    for (int off = 1; off < SCB; off <<= 1) {
        int u = (t >= off) ? sh[t - off] : 0;
        __syncthreads();
        sh[t] += u;
        __syncthreads();
    }
    d_pbase[t] = sh[t] - v;
    if (t == SCB - 1) d_rs[NN] = sh[SCB - 1];
}

__global__ void __launch_bounds__(256) k_scan3() {
    __shared__ int sh[256];
    int t = threadIdx.x;
    int i0 = blockIdx.x * 1024 + t * 4;
    int s = scan_chunk_sum(i0);
    sh[t] = s;
    __syncthreads();
    for (int off = 1; off < 256; off <<= 1) {
        int u = (t >= off) ? sh[t - off] : 0;
        __syncthreads();
        sh[t] += u;
        __syncthreads();
    }
    int run = d_pbase[blockIdx.x] + sh[t] - s;
#pragma unroll
    for (int j = 0; j < 4; j++) {
        int i = i0 + j;
        if (i < NN) {
            d_rs[i] = run;
            d_cur[i] = run;
            run += d_cnt[i];
        }
    }
}

// ---------------- precompute folded constants ----------------
__global__ void __launch_bounds__(256) k_pre(const float* __restrict__ W1,
                                             const float* __restrict__ as1,
                                             const float* __restrict__ ad1,
                                             const float* __restrict__ We1,
                                             const float* __restrict__ ae1,
                                             const float* __restrict__ We2,
                                             const float* __restrict__ ae2,
                                             const float* __restrict__ b1,
                                             const float* __restrict__ W2) {
    int t = threadIdx.x;
    if (t < 4) {
        float s = 0;
        for (int d = 0; d < 64; d++) s += W1[t * 64 + d] * as1[t * 64 + d];
        d_u0[t] = s;
    } else if (t < 8) {
        int h = t - 4;
        float s = 0;
        for (int d = 0; d < 64; d++) s += W1[256 + h * 64 + d] * as1[h * 64 + d];
        d_u1[h] = s;
    } else if (t < 12) {
        int h = t - 8;
        float s = 0;
        for (int d = 0; d < 64; d++) s += W1[h * 64 + d] * ad1[h * 64 + d];
        d_v0[h] = s;
    } else if (t < 16) {
        int h = t - 12;
        float s = 0;
        for (int d = 0; d < 64; d++) s += W1[256 + h * 64 + d] * ad1[h * 64 + d];
        d_v1[h] = s;
    } else if (t < 20) {
        int h = t - 16;
        float s = 0;
        for (int d = 0; d < 64; d++) s += We1[h * 64 + d] * ae1[h * 64 + d];
        d_c1[h] = s;
    } else if (t == 20) {
        float s = 0;
        for (int d = 0; d < 64; d++) s += We2[d] * ae2[d];
        d_c2s = s;
    }
    if (t >= 64 && t < 128) {
        int j = t - 64;
        float s = 0;
        for (int c = 0; c < 256; c++) s += b1[c] * W2[c * 64 + j];
        d_bvec[j] = s;
    }
#pragma unroll
    for (int rep = 0; rep < 2; rep++) {
        int idx = rep * 256 + t;
        int i = idx >> 8, rem = idx & 255, h = rem >> 6, j = rem & 63;
        float s = 0;
        for (int d = 0; d < 64; d++)
            s += W1[i * 256 + h * 64 + d] * W2[(h * 64 + d) * 64 + j];
        d_G[idx] = s;
    }
}

// ---------------- fill CSR buckets (packed record) ----------------
__global__ void __launch_bounds__(256) k_fill(const int* __restrict__ ei,
                                              const float* __restrict__ attr) {
    int e = blockIdx.x * 256 + threadIdx.x;
    if (e >= NE) return;
    int s = ei[e], dd = ei[NE + e];
    if ((unsigned)s >= NN || (unsigned)dd >= NN) return;
    int pos = atomicAdd(&d_cur[dd], 1);
    if ((unsigned)pos >= NE) return;
    d_pack[pos] = make_int4(s, dd, e, __float_as_int(attr[e]));
}

// ---------------- layer-1: single-pass softmax + rank-2 agg + @W2 + dots ---
__global__ void __launch_bounds__(256) k_agg1(const float* __restrict__ x,
                                              const float* __restrict__ as2,
                                              const float* __restrict__ ad2) {
    int warp = threadIdx.x >> 5, lane = threadIdx.x & 31;
    int n = blockIdx.x * 8 + warp;   // grid exact
    int r0 = d_rs[n], r1 = d_rs[n + 1];

    float2 xn = __ldg((const float2*)x + n);
    float adh[4], u0[4], u1[4], c1[4];
#pragma unroll
    for (int h = 0; h < 4; h++) {
        u0[h] = d_u0[h]; u1[h] = d_u1[h]; c1[h] = d_c1[h];
        adh[h] = xn.x * d_v0[h] + xn.y * d_v1[h];
    }

    // single pass: unnormalized exp-weights (logits bounded; no max needed)
    float z[4] = {0, 0, 0, 0};
    float acc[8] = {0, 0, 0, 0, 0, 0, 0, 0};
    for (int pos = r0 + lane; pos < r1; pos += 32) {
        int4 p = __ldg(&d_pack[pos]);
        float a = __int_as_float(p.w);
        float2 xs = __ldg((const float2*)x + p.x);
#pragma unroll
        for (int h = 0; h < 4; h++) {
            float lg = lrelu(xs.x * u0[h] + xs.y * u1[h] + adh[h] + a * c1[h]);
            float w = __expf(lg);
            z[h] += w;
            acc[2 * h] += w * xs.x;
            acc[2 * h + 1] += w * xs.y;
        }
    }
#pragma unroll
    for (int off = 16; off; off >>= 1) {
#pragma unroll
        for (int h = 0; h < 4; h++)
            z[h] += __shfl_xor_sync(0xffffffffu, z[h], off);
#pragma unroll
        for (int q = 0; q < 8; q++)
            acc[q] += __shfl_xor_sync(0xffffffffu, acc[q], off);
    }
    float S[8];
#pragma unroll
    for (int h = 0; h < 4; h++) {
        float rz = 1.f / (z[h] + 1e-16f);
        S[2 * h] = acc[2 * h] * rz;
        S[2 * h + 1] = acc[2 * h + 1] * rz;
    }

    int j0 = 2 * lane;
    float h0 = __ldg(&d_bvec[j0]), h1v = __ldg(&d_bvec[j0 + 1]);
#pragma unroll
    for (int h = 0; h < 4; h++) {
#pragma unroll
        for (int i = 0; i < 2; i++) {
            float2 g = *(const float2*)(d_G + (i * 4 + h) * 64 + j0);
            float sv = S[2 * h + i];
            h0 += sv * g.x;
            h1v += sv * g.y;
        }
    }
    *(float2*)(d_h2 + (long)n * 64 + j0) = make_float2(h0, h1v);

    float2 a2 = __ldg((const float2*)as2 + lane);
    float2 dd2 = __ldg((const float2*)ad2 + lane);
    float pa = h0 * a2.x + h1v * a2.y;
    float pd = h0 * dd2.x + h1v * dd2.y;
#pragma unroll
    for (int off = 16; off; off >>= 1) {
        pa += __shfl_xor_sync(0xffffffffu, pa, off);
        pd += __shfl_xor_sync(0xffffffffu, pd, off);
    }
    if (lane == 0) {
        d_als2[n] = pa;
        d_ald2[n] = pd;
    }
}

// ---------------- layer-2: single-pass softmax + agg (chunked shuffle) -----
__global__ void __launch_bounds__(256) k_agg2(const float* __restrict__ b2) {
    int t = threadIdx.x;
    int warp = t >> 5, lane = t & 31;
    int n = blockIdx.x * 8 + warp;   // grid exact
    int r0 = d_rs[n], r1 = d_rs[n + 1];
    float aldn = d_ald2[n];
    float c2 = d_c2s;

    int c0 = lane * 2;
    float a0 = 0.f, a1 = 0.f, zsum = 0.f;
    for (int chunk = r0; chunk < r1; chunk += 32) {
        int pos = chunk + lane;
        float w = 0.f;
        int s = 0;
        if (pos < r1) {
            int4 p = __ldg(&d_pack[pos]);
            s = p.x;
            float a = __int_as_float(p.w);
            float lg = lrelu(__ldg(&d_als2[s]) + aldn + a * c2);
            w = __expf(lg);
        }
        zsum += w;
        int nj = min(32, r1 - chunk);
        for (int j = 0; j < nj; j++) {
            float wj = __shfl_sync(0xffffffffu, w, j);
            int sj = __shfl_sync(0xffffffffu, s, j);
            float2 v = *(const float2*)(d_h2 + (long)sj * 64 + c0);
            a0 += wj * v.x;
            a1 += wj * v.y;
        }
    }
#pragma unroll
    for (int off = 16; off; off >>= 1)
        zsum += __shfl_xor_sync(0xffffffffu, zsum, off);
    float rz = 1.f / (zsum + 1e-16f);

    float2 bb = __ldg((const float2*)(b2 + c0));
    *(float2*)(d_out2 + (long)n * 64 + c0) =
        make_float2(a0 * rz + bb.x, a1 * rz + bb.y);
}

// ---------------- GEMM: d_gv[N,64] = d_out2[N,64] @ Wr1 ----------------
__global__ void __launch_bounds__(256) k_gemm2(const float* __restrict__ B) {
    __shared__ float sA[64][65];
    __shared__ float sB[64][64];
    int t = threadIdx.x;
    int r = t & 63, cg = t >> 6, c0 = cg * 16;
    int row0 = blockIdx.x * 64;
    float acc[16];
#pragma unroll
    for (int j = 0; j < 16; j++) acc[j] = 0.f;

#pragma unroll
    for (int i = 0; i < 16; i++) {
        int lin = i * 256 + t;
        int rr = lin >> 6, cc = lin & 63;
        int grow = row0 + rr;
        sA[rr][cc] = (grow < NN) ? d_out2[(long)grow * 64 + cc] : 0.f;
        sB[rr][cc] = B[(long)rr * 64 + cc];
    }
    __syncthreads();
#pragma unroll
    for (int k2 = 0; k2 < 64; k2++) {
        float a = sA[r][k2];
#pragma unroll
        for (int j = 0; j < 16; j++) acc[j] += a * sB[k2][c0 + j];
    }
    int grow = row0 + r;
    if (grow < NN) {
        float4* cp = (float4*)(d_gv + (long)grow * 64 + c0);
        cp[0] = make_float4(acc[0], acc[1], acc[2], acc[3]);
        cp[1] = make_float4(acc[4], acc[5], acc[6], acc[7]);
        cp[2] = make_float4(acc[8], acc[9], acc[10], acc[11]);
        cp[3] = make_float4(acc[12], acc[13], acc[14], acc[15]);
    }
}

// ---------------- final edge regressor (CSR order; 8 lanes per edge) -------
__global__ void __launch_bounds__(256) k_edge(const float* __restrict__ br1,
                                              const float* __restrict__ Wr2,
                                              const float* __restrict__ br2,
                                              float* __restrict__ out) {
    int t = blockIdx.x * 256 + threadIdx.x;
    int pos = t >> 3;
    if (pos >= NE) return;
    int o = t & 7;
    int4 p = __ldg(&d_pack[pos]);
    int s = p.x, dd = p.y;
    int c0 = o * 8;
    const float4* gs = (const float4*)(d_gv + (long)s * 64 + c0);
    const float4* gd = (const float4*)(d_gv + (long)dd * 64 + c0);
    float4 s0 = __ldg(gs), s1 = __ldg(gs + 1);
    float4 t0 = __ldg(gd), t1 = __ldg(gd + 1);
    float4 w0 = __ldg((const float4*)(Wr2 + c0)), w1 = __ldg((const float4*)(Wr2 + c0 + 4));
    float4 r0 = __ldg((const float4*)(br1 + c0)), r1 = __ldg((const float4*)(br1 + c0 + 4));
    float pv = 0.f;
    pv += fmaxf(s0.x + t0.x + r0.x, 0.f) * w0.x;
    pv += fmaxf(s0.y + t0.y + r0.y, 0.f) * w0.y;
    pv += fmaxf(s0.z + t0.z + r0.z, 0.f) * w0.z;
    pv += fmaxf(s0.w + t0.w + r0.w, 0.f) * w0.w;
    pv += fmaxf(s1.x + t1.x + r1.x, 0.f) * w1.x;
    pv += fmaxf(s1.y + t1.y + r1.y, 0.f) * w1.y;
    pv += fmaxf(s1.z + t1.z + r1.z, 0.f) * w1.z;
    pv += fmaxf(s1.w + t1.w + r1.w, 0.f) * w1.w;
#pragma unroll
    for (int off = 4; off; off >>= 1) pv += __shfl_down_sync(0xffffffffu, pv, off);
    if (o == 0) out[p.z] = pv + __ldg(br2);
}

// ---------------- host diagnostics (static; no allocation) -----------------
static int   h_rs[1];
static float h_h2[2], h_gv[2], h_out[8];

// ---------------- launch ----------------
extern "C" void kernel_launch(void* const* d_in, const int* in_sizes, int n_in,
                              void* d_out, int out_size) {
    const float* x    = (const float*)d_in[0];
    const int*   ei   = (const int*)d_in[1];
    const float* attr = (const float*)d_in[2];
    const float* W1   = (const float*)d_in[3];
    const float* We1  = (const float*)d_in[4];
    const float* as1  = (const float*)d_in[5];
    const float* ad1  = (const float*)d_in[6];
    const float* ae1  = (const float*)d_in[7];
    const float* b1   = (const float*)d_in[8];
    const float* W2   = (const float*)d_in[9];
    const float* We2  = (const float*)d_in[10];
    const float* as2  = (const float*)d_in[11];
    const float* ad2  = (const float*)d_in[12];
    const float* ae2  = (const float*)d_in[13];
    const float* b2   = (const float*)d_in[14];
    const float* Wr1  = (const float*)d_in[15];
    const float* br1  = (const float*)d_in[16];
    const float* Wr2  = (const float*)d_in[17];
    const float* br2  = (const float*)d_in[18];
    float* out = (float*)d_out;

    const int EB = (NE + 255) / 256;
    const int NB8 = (NN + 7) / 8;     // 12500 exact
    const int NB64 = (NN + 63) / 64;
    const int ZB = (NN + 255) / 256;

    k_zero<<<ZB, 256>>>();
    k_count<<<EB, 256>>>(ei);
    k_pre<<<1, 256>>>(W1, as1, ad1, We1, ae1, We2, ae2, b1, W2);
    k_scan1<<<SCB, 256>>>();
    k_scan2<<<1, SCB>>>();
    k_scan3<<<SCB, 256>>>();
    k_fill<<<EB, 256>>>(ei, attr);
    k_agg1<<<NB8, 256>>>(x, as2, ad2);
    k_agg2<<<NB8, 256>>>(b2);
    k_gemm2<<<NB64, 256>>>(Wr1);
    k_edge<<<(NE * 8 + 255) / 256, 256>>>(br1, Wr2, br2, out);

    // -------- slim health check: only on the non-capture correctness call --
    cudaStreamCaptureStatus cs = cudaStreamCaptureStatusNone;
    cudaStreamIsCapturing((cudaStream_t)0, &cs);
    if (cs != cudaStreamCaptureStatusNone) return;

    h_rs[0] = -777;
    cudaMemcpyFromSymbolAsync(h_rs, d_rs, 4, (size_t)NN * 4, cudaMemcpyDeviceToHost, 0);
    cudaMemcpyFromSymbolAsync(h_h2, d_h2, 8, 0, cudaMemcpyDeviceToHost, 0);
    cudaMemcpyFromSymbolAsync(h_gv, d_gv, 8, 0, cudaMemcpyDeviceToHost, 0);
    cudaMemcpyAsync(h_out, out, 32, cudaMemcpyDeviceToHost, 0);
    cudaError_t sticky = cudaGetLastError();

    float omax = 0.f;
    bool ofin = true;
    for (int i = 0; i < 8; i++) {
        if (!isfinite(h_out[i])) ofin = false;
        float a = fabsf(h_out[i]);
        if (a > omax) omax = a;
    }
    bool healthy = sticky == cudaSuccess && h_rs[0] == NE && ofin &&
                   omax > 1e-30f &&
                   (fabsf(h_h2[0]) + fabsf(h_h2[1])) > 0.f &&
                   (fabsf(h_gv[0]) + fabsf(h_gv[1])) > 0.f;
    if (healthy) return;

    for (int pass = 0; pass < 2; pass++) {
        FILE* f = pass ? stderr : stdout;
        fprintf(f, "DG sticky=%d(%s) rsN=%d h2=[%g %g] gv=[%g %g] out=[%g %g %g %g]\n",
                (int)sticky, cudaGetErrorString(sticky), h_rs[0],
                h_h2[0], h_h2[1], h_gv[0], h_gv[1],
                h_out[0], h_out[1], h_out[2], h_out[3]);
        fflush(f);
    }
    abort();
}

// round 11
// speedup vs baseline: 1.5172x; 1.1509x over previous
#include <cuda_runtime.h>
#include <cstdio>
#include <cstdlib>
#include <math.h>

#define NN 100000
#define NE 1600000
#define HIDD 64
#define NEGS 0.2f
#define SCB 128   // scan blocks (128*256*4 = 131072 >= NN)

// ---------------- scratch (device globals; zero-init at load) --------------
__device__ __align__(16) int   d_cnt[NN];     // re-zeroed by k_scan3 each run
__device__ __align__(16) int   d_rs[NN + 1];
__device__ __align__(16) int   d_cur[NN];
__device__ __align__(16) int   d_part[SCB];
__device__ __align__(16) int   d_pbase[SCB];
__device__ __align__(16) int2  d_sa[NE];      // {src, attr-bits}, dst-sorted
__device__ __align__(16) int   d_eid[NE];     // original edge id, dst-sorted
__device__ __align__(16) float d_h2[NN * HIDD];
__device__ __align__(16) float d_als2[NN];
__device__ __align__(16) float d_ald2[NN];
__device__ __align__(16) float d_out2[NN * HIDD];
__device__ __align__(16) float d_gv[NN * HIDD];
// folded layer-1 constants
__device__ __align__(16) float d_u0[4], d_u1[4];
__device__ __align__(16) float d_v0[4], d_v1[4];
__device__ __align__(16) float d_c1[4];
__device__ float d_c2s;
__device__ __align__(16) float d_G[512];
__device__ __align__(16) float d_bvec[64];

__device__ __forceinline__ float lrelu(float x) { return x > 0.f ? x : NEGS * x; }

// ---------------- CSR build ----------------
__global__ void __launch_bounds__(256) k_count(const int* __restrict__ ei) {
    int e = blockIdx.x * 256 + threadIdx.x;
    if (e < NE) {
        int d = ei[NE + e];
        if ((unsigned)d < NN) atomicAdd(&d_cnt[d], 1);
    }
}

__device__ __forceinline__ int scan_chunk_sum(int i0) {
    int s = 0;
#pragma unroll
    for (int j = 0; j < 4; j++) {
        int i = i0 + j;
        if (i < NN) s += d_cnt[i];
    }
    return s;
}

__global__ void __launch_bounds__(256) k_scan1() {
    __shared__ int sh[256];
    int t = threadIdx.x;
    int i0 = blockIdx.x * 1024 + t * 4;
    sh[t] = scan_chunk_sum(i0);
    __syncthreads();
    for (int off = 128; off; off >>= 1) {
        if (t < off) sh[t] += sh[t + off];
        __syncthreads();
    }
    if (t == 0) d_part[blockIdx.x] = sh[0];
}

__global__ void __launch_bounds__(SCB) k_scan2() {
    __shared__ int sh[SCB];
    int t = threadIdx.x;
    int v = d_part[t];
    sh[t] = v;
    __syncthreads();
    for (int off = 1; off < SCB; off <<= 1) {
        int u = (t >= off) ? sh[t - off] : 0;
        __syncthreads();
        sh[t] += u;
        __syncthreads();
    }
    d_pbase[t] = sh[t] - v;
    if (t == SCB - 1) d_rs[NN] = sh[SCB - 1];
}

__global__ void __launch_bounds__(256) k_scan3() {
    __shared__ int sh[256];
    int t = threadIdx.x;
    int i0 = blockIdx.x * 1024 + t * 4;
    int s = scan_chunk_sum(i0);
    sh[t] = s;
    __syncthreads();
    for (int off = 1; off < 256; off <<= 1) {
        int u = (t >= off) ? sh[t - off] : 0;
        __syncthreads();
        sh[t] += u;
        __syncthreads();
    }
    int run = d_pbase[blockIdx.x] + sh[t] - s;
#pragma unroll
    for (int j = 0; j < 4; j++) {
        int i = i0 + j;
        if (i < NN) {
            d_rs[i] = run;
            d_cur[i] = run;
            run += d_cnt[i];
            d_cnt[i] = 0;   // self-clean for next graph replay
        }
    }
}

// ---------------- precompute folded constants ----------------
__global__ void __launch_bounds__(256) k_pre(const float* __restrict__ W1,
                                             const float* __restrict__ as1,
                                             const float* __restrict__ ad1,
                                             const float* __restrict__ We1,
                                             const float* __restrict__ ae1,
                                             const float* __restrict__ We2,
                                             const float* __restrict__ ae2,
                                             const float* __restrict__ b1,
                                             const float* __restrict__ W2) {
    int t = threadIdx.x;
    if (t < 4) {
        float s = 0;
        for (int d = 0; d < 64; d++) s += W1[t * 64 + d] * as1[t * 64 + d];
        d_u0[t] = s;
    } else if (t < 8) {
        int h = t - 4;
        float s = 0;
        for (int d = 0; d < 64; d++) s += W1[256 + h * 64 + d] * as1[h * 64 + d];
        d_u1[h] = s;
    } else if (t < 12) {
        int h = t - 8;
        float s = 0;
        for (int d = 0; d < 64; d++) s += W1[h * 64 + d] * ad1[h * 64 + d];
        d_v0[h] = s;
    } else if (t < 16) {
        int h = t - 12;
        float s = 0;
        for (int d = 0; d < 64; d++) s += W1[256 + h * 64 + d] * ad1[h * 64 + d];
        d_v1[h] = s;
    } else if (t < 20) {
        int h = t - 16;
        float s = 0;
        for (int d = 0; d < 64; d++) s += We1[h * 64 + d] * ae1[h * 64 + d];
        d_c1[h] = s;
    } else if (t == 20) {
        float s = 0;
        for (int d = 0; d < 64; d++) s += We2[d] * ae2[d];
        d_c2s = s;
    }
    if (t >= 64 && t < 128) {
        int j = t - 64;
        float s = 0;
        for (int c = 0; c < 256; c++) s += b1[c] * W2[c * 64 + j];
        d_bvec[j] = s;
    }
#pragma unroll
    for (int rep = 0; rep < 2; rep++) {
        int idx = rep * 256 + t;
        int i = idx >> 8, rem = idx & 255, h = rem >> 6, j = rem & 63;
        float s = 0;
        for (int d = 0; d < 64; d++)
            s += W1[i * 256 + h * 64 + d] * W2[(h * 64 + d) * 64 + j];
        d_G[idx] = s;
    }
}

// ---------------- fill CSR buckets (slim records) ----------------
__global__ void __launch_bounds__(256) k_fill(const int* __restrict__ ei,
                                              const float* __restrict__ attr) {
    int e = blockIdx.x * 256 + threadIdx.x;
    if (e >= NE) return;
    int s = ei[e], dd = ei[NE + e];
    if ((unsigned)s >= NN || (unsigned)dd >= NN) return;
    int pos = atomicAdd(&d_cur[dd], 1);
    if ((unsigned)pos >= NE) return;
    d_sa[pos] = make_int2(s, __float_as_int(attr[e]));
    d_eid[pos] = e;
}

// ---------------- layer-1: single-pass softmax + rank-2 agg + @W2 + dots ---
__global__ void __launch_bounds__(256) k_agg1(const float* __restrict__ x,
                                              const float* __restrict__ as2,
                                              const float* __restrict__ ad2) {
    int warp = threadIdx.x >> 5, lane = threadIdx.x & 31;
    int n = blockIdx.x * 8 + warp;   // grid exact
    int r0 = d_rs[n], r1 = d_rs[n + 1];

    float2 xn = __ldg((const float2*)x + n);
    float adh[4], u0[4], u1[4], c1[4];
#pragma unroll
    for (int h = 0; h < 4; h++) {
        u0[h] = d_u0[h]; u1[h] = d_u1[h]; c1[h] = d_c1[h];
        adh[h] = xn.x * d_v0[h] + xn.y * d_v1[h];
    }

    float z[4] = {0, 0, 0, 0};
    float acc[8] = {0, 0, 0, 0, 0, 0, 0, 0};
    for (int pos = r0 + lane; pos < r1; pos += 32) {
        int2 p = __ldg(&d_sa[pos]);
        float a = __int_as_float(p.y);
        float2 xs = __ldg((const float2*)x + p.x);
#pragma unroll
        for (int h = 0; h < 4; h++) {
            float lg = lrelu(xs.x * u0[h] + xs.y * u1[h] + adh[h] + a * c1[h]);
            float w = __expf(lg);
            z[h] += w;
            acc[2 * h] += w * xs.x;
            acc[2 * h + 1] += w * xs.y;
        }
    }
#pragma unroll
    for (int off = 16; off; off >>= 1) {
#pragma unroll
        for (int h = 0; h < 4; h++)
            z[h] += __shfl_xor_sync(0xffffffffu, z[h], off);
#pragma unroll
        for (int q = 0; q < 8; q++)
            acc[q] += __shfl_xor_sync(0xffffffffu, acc[q], off);
    }
    float S[8];
#pragma unroll
    for (int h = 0; h < 4; h++) {
        float rz = 1.f / (z[h] + 1e-16f);
        S[2 * h] = acc[2 * h] * rz;
        S[2 * h + 1] = acc[2 * h + 1] * rz;
    }

    int j0 = 2 * lane;
    float h0 = __ldg(&d_bvec[j0]), h1v = __ldg(&d_bvec[j0 + 1]);
#pragma unroll
    for (int h = 0; h < 4; h++) {
#pragma unroll
        for (int i = 0; i < 2; i++) {
            float2 g = *(const float2*)(d_G + (i * 4 + h) * 64 + j0);
            float sv = S[2 * h + i];
            h0 += sv * g.x;
            h1v += sv * g.y;
        }
    }
    *(float2*)(d_h2 + (long)n * 64 + j0) = make_float2(h0, h1v);

    float2 a2 = __ldg((const float2*)as2 + lane);
    float2 dd2 = __ldg((const float2*)ad2 + lane);
    float pa = h0 * a2.x + h1v * a2.y;
    float pd = h0 * dd2.x + h1v * dd2.y;
#pragma unroll
    for (int off = 16; off; off >>= 1) {
        pa += __shfl_xor_sync(0xffffffffu, pa, off);
        pd += __shfl_xor_sync(0xffffffffu, pd, off);
    }
    if (lane == 0) {
        d_als2[n] = pa;
        d_ald2[n] = pd;
    }
}

// ---------------- layer-2: single-pass softmax + agg (chunked shuffle) -----
__global__ void __launch_bounds__(256) k_agg2(const float* __restrict__ b2) {
    int t = threadIdx.x;
    int warp = t >> 5, lane = t & 31;
    int n = blockIdx.x * 8 + warp;   // grid exact
    int r0 = d_rs[n], r1 = d_rs[n + 1];
    float aldn = d_ald2[n];
    float c2 = d_c2s;

    int c0 = lane * 2;
    float a0 = 0.f, a1 = 0.f, zsum = 0.f;
    for (int chunk = r0; chunk < r1; chunk += 32) {
        int pos = chunk + lane;
        float w = 0.f;
        int s = 0;
        if (pos < r1) {
            int2 p = __ldg(&d_sa[pos]);
            s = p.x;
            float a = __int_as_float(p.y);
            float lg = lrelu(__ldg(&d_als2[s]) + aldn + a * c2);
            w = __expf(lg);
        }
        zsum += w;
        int nj = min(32, r1 - chunk);
        for (int j = 0; j < nj; j++) {
            float wj = __shfl_sync(0xffffffffu, w, j);
            int sj = __shfl_sync(0xffffffffu, s, j);
            float2 v = *(const float2*)(d_h2 + (long)sj * 64 + c0);
            a0 += wj * v.x;
            a1 += wj * v.y;
        }
    }
#pragma unroll
    for (int off = 16; off; off >>= 1)
        zsum += __shfl_xor_sync(0xffffffffu, zsum, off);
    float rz = 1.f / (zsum + 1e-16f);

    float2 bb = __ldg((const float2*)(b2 + c0));
    *(float2*)(d_out2 + (long)n * 64 + c0) =
        make_float2(a0 * rz + bb.x, a1 * rz + bb.y);
}

// ---------------- GEMM: d_gv[N,64] = d_out2[N,64] @ Wr1 ----------------
__global__ void __launch_bounds__(256) k_gemm2(const float* __restrict__ B) {
    __shared__ float sA[64][65];
    __shared__ float sB[64][64];
    int t = threadIdx.x;
    int r = t & 63, cg = t >> 6, c0 = cg * 16;
    int row0 = blockIdx.x * 64;
    float acc[16];
#pragma unroll
    for (int j = 0; j < 16; j++) acc[j] = 0.f;

#pragma unroll
    for (int i = 0; i < 16; i++) {
        int lin = i * 256 + t;
        int rr = lin >> 6, cc = lin & 63;
        int grow = row0 + rr;
        sA[rr][cc] = (grow < NN) ? d_out2[(long)grow * 64 + cc] : 0.f;
        sB[rr][cc] = B[(long)rr * 64 + cc];
    }
    __syncthreads();
#pragma unroll
    for (int k2 = 0; k2 < 64; k2++) {
        float a = sA[r][k2];
#pragma unroll
        for (int j = 0; j < 16; j++) acc[j] += a * sB[k2][c0 + j];
    }
    int grow = row0 + r;
    if (grow < NN) {
        float4* cp = (float4*)(d_gv + (long)grow * 64 + c0);
        cp[0] = make_float4(acc[0], acc[1], acc[2], acc[3]);
        cp[1] = make_float4(acc[4], acc[5], acc[6], acc[7]);
        cp[2] = make_float4(acc[8], acc[9], acc[10], acc[11]);
        cp[3] = make_float4(acc[12], acc[13], acc[14], acc[15]);
    }
}

// ---------------- final edge regressor (warp per dst node) ----------------
__global__ void __launch_bounds__(256) k_edge(const float* __restrict__ br1,
                                              const float* __restrict__ Wr2,
                                              const float* __restrict__ br2,
                                              float* __restrict__ out) {
    int warp = threadIdx.x >> 5, lane = threadIdx.x & 31;
    int n = blockIdx.x * 8 + warp;   // grid exact
    int r0 = d_rs[n], r1 = d_rs[n + 1];
    if (r0 >= r1) return;
    int c0 = lane * 2;
    float2 gd = *(const float2*)(d_gv + (long)n * 64 + c0);
    float2 rb = __ldg((const float2*)(br1 + c0));
    float2 w2 = __ldg((const float2*)(Wr2 + c0));
    float base0 = gd.x + rb.x, base1 = gd.y + rb.y;
    float brv = __ldg(br2);

    for (int pos = r0; pos < r1; pos += 2) {
        int sA = __ldg(&d_sa[pos]).x;
        float2 ga = *(const float2*)(d_gv + (long)sA * 64 + c0);
        float pa = fmaxf(ga.x + base0, 0.f) * w2.x + fmaxf(ga.y + base1, 0.f) * w2.y;
        bool hasB = (pos + 1) < r1;
        float pb = 0.f;
        if (hasB) {
            int sB = __ldg(&d_sa[pos + 1]).x;
            float2 gb = *(const float2*)(d_gv + (long)sB * 64 + c0);
            pb = fmaxf(gb.x + base0, 0.f) * w2.x + fmaxf(gb.y + base1, 0.f) * w2.y;
        }
#pragma unroll
        for (int off = 16; off; off >>= 1) {
            pa += __shfl_xor_sync(0xffffffffu, pa, off);
            pb += __shfl_xor_sync(0xffffffffu, pb, off);
        }
        if (lane == 0) out[__ldg(&d_eid[pos])] = pa + brv;
        if (hasB && lane == 1) out[__ldg(&d_eid[pos + 1])] = pb + brv;
    }
}

// ---------------- host diagnostics (static; no allocation) -----------------
static int   h_rs[1];
static float h_h2[2], h_gv[2], h_out[8];

// ---------------- launch ----------------
extern "C" void kernel_launch(void* const* d_in, const int* in_sizes, int n_in,
                              void* d_out, int out_size) {
    const float* x    = (const float*)d_in[0];
    const int*   ei   = (const int*)d_in[1];
    const float* attr = (const float*)d_in[2];
    const float* W1   = (const float*)d_in[3];
    const float* We1  = (const float*)d_in[4];
    const float* as1  = (const float*)d_in[5];
    const float* ad1  = (const float*)d_in[6];
    const float* ae1  = (const float*)d_in[7];
    const float* b1   = (const float*)d_in[8];
    const float* W2   = (const float*)d_in[9];
    const float* We2  = (const float*)d_in[10];
    const float* as2  = (const float*)d_in[11];
    const float* ad2  = (const float*)d_in[12];
    const float* ae2  = (const float*)d_in[13];
    const float* b2   = (const float*)d_in[14];
    const float* Wr1  = (const float*)d_in[15];
    const float* br1  = (const float*)d_in[16];
    const float* Wr2  = (const float*)d_in[17];
    const float* br2  = (const float*)d_in[18];
    float* out = (float*)d_out;

    const int EB = (NE + 255) / 256;
    const int NB8 = (NN + 7) / 8;     // 12500 exact
    const int NB64 = (NN + 63) / 64;

    k_count<<<EB, 256>>>(ei);
    k_pre<<<1, 256>>>(W1, as1, ad1, We1, ae1, We2, ae2, b1, W2);
    k_scan1<<<SCB, 256>>>();
    k_scan2<<<1, SCB>>>();
    k_scan3<<<SCB, 256>>>();
    k_fill<<<EB, 256>>>(ei, attr);
    k_agg1<<<NB8, 256>>>(x, as2, ad2);
    k_agg2<<<NB8, 256>>>(b2);
    k_gemm2<<<NB64, 256>>>(Wr1);
    k_edge<<<NB8, 256>>>(br1, Wr2, br2, out);

    // -------- slim health check: only on the non-capture correctness call --
    cudaStreamCaptureStatus cs = cudaStreamCaptureStatusNone;
    cudaStreamIsCapturing((cudaStream_t)0, &cs);
    if (cs != cudaStreamCaptureStatusNone) return;

    h_rs[0] = -777;
    cudaMemcpyFromSymbolAsync(h_rs, d_rs, 4, (size_t)NN * 4, cudaMemcpyDeviceToHost, 0);
    cudaMemcpyFromSymbolAsync(h_h2, d_h2, 8, 0, cudaMemcpyDeviceToHost, 0);
    cudaMemcpyFromSymbolAsync(h_gv, d_gv, 8, 0, cudaMemcpyDeviceToHost, 0);
    cudaMemcpyAsync(h_out, out, 32, cudaMemcpyDeviceToHost, 0);
    cudaError_t sticky = cudaGetLastError();

    float omax = 0.f;
    bool ofin = true;
    for (int i = 0; i < 8; i++) {
        if (!isfinite(h_out[i])) ofin = false;
        float a = fabsf(h_out[i]);
        if (a > omax) omax = a;
    }
    bool healthy = sticky == cudaSuccess && h_rs[0] == NE && ofin &&
                   omax > 1e-30f &&
                   (fabsf(h_h2[0]) + fabsf(h_h2[1])) > 0.f &&
                   (fabsf(h_gv[0]) + fabsf(h_gv[1])) > 0.f;
    if (healthy) return;

    for (int pass = 0; pass < 2; pass++) {
        FILE* f = pass ? stderr : stdout;
        fprintf(f, "DG sticky=%d(%s) rsN=%d h2=[%g %g] gv=[%g %g] out=[%g %g %g %g]\n",
                (int)sticky, cudaGetErrorString(sticky), h_rs[0],
                h_h2[0], h_h2[1], h_gv[0], h_gv[1],
                h_out[0], h_out[1], h_out[2], h_out[3]);
        fflush(f);
    }
    abort();
}

// round 12
// speedup vs baseline: 1.8258x; 1.2034x over previous
#include <cuda_runtime.h>
#include <cstdio>
#include <cstdlib>
#include <math.h>

#define NN 100000
#define NE 1600000
#define NEGS 0.2f
#define SCB 128   // scan blocks (128*256*4 = 131072 >= NN)

// ---------------- scratch (device globals; zero-init at load) --------------
__device__ __align__(16) int   d_cnt[NN];     // re-zeroed by k_scan3 each run
__device__ __align__(16) int   d_rs[NN + 1];
__device__ __align__(16) int   d_cur[NN];
__device__ __align__(16) int   d_part[SCB];
__device__ __align__(16) int   d_pbase[SCB];
__device__ __align__(16) int2  d_sa[NE];      // {src, attr-bits}, dst-sorted
__device__ __align__(16) int   d_eid[NE];     // original edge id, dst-sorted
__device__ __align__(16) float d_S[NN * 8];   // layer-1 per-node aggregates (q=i*4+h)
__device__ __align__(16) float d_T[NN * 8];   // layer-2 per-node aggregates
__device__ __align__(16) float d_Ts[NN];      // 1 if node has incoming edges
__device__ __align__(16) float d_als2[NN];
__device__ __align__(16) float d_ald2[NN];
__device__ __align__(16) float d_gv[NN * 64];
// folded constants
__device__ __align__(16) float d_u0[4], d_u1[4];
__device__ __align__(16) float d_v0[4], d_v1[4];
__device__ __align__(16) float d_c1[4];
__device__ float d_c2s;
__device__ __align__(16) float d_G[512];      // [q][j], q = i*4+h
__device__ __align__(16) float d_bvec[64];    // b1 @ W2
__device__ __align__(16) float d_gA[8], d_gD[8];   // G @ as2, G @ ad2
__device__ float d_cA, d_cD;                       // bvec·as2, bvec·ad2
__device__ __align__(16) float d_GW[512];     // [q][j] = G[q,:] @ Wr1
__device__ __align__(16) float d_bB2[64];     // b2 @ Wr1
__device__ __align__(16) float d_bBV[64];     // bvec @ Wr1

__device__ __forceinline__ float lrelu(float x) { return x > 0.f ? x : NEGS * x; }

// ---------------- CSR build ----------------
__global__ void __launch_bounds__(256) k_count(const int* __restrict__ ei) {
    int e = blockIdx.x * 256 + threadIdx.x;
    if (e < NE) {
        int d = ei[NE + e];
        if ((unsigned)d < NN) atomicAdd(&d_cnt[d], 1);
    }
}

__device__ __forceinline__ int scan_chunk_sum(int i0) {
    int s = 0;
#pragma unroll
    for (int j = 0; j < 4; j++) {
        int i = i0 + j;
        if (i < NN) s += d_cnt[i];
    }
    return s;
}

__global__ void __launch_bounds__(256) k_scan1() {
    __shared__ int sh[256];
    int t = threadIdx.x;
    int i0 = blockIdx.x * 1024 + t * 4;
    sh[t] = scan_chunk_sum(i0);
    __syncthreads();
    for (int off = 128; off; off >>= 1) {
        if (t < off) sh[t] += sh[t + off];
        __syncthreads();
    }
    if (t == 0) d_part[blockIdx.x] = sh[0];
}

__global__ void __launch_bounds__(SCB) k_scan2() {
    __shared__ int sh[SCB];
    int t = threadIdx.x;
    int v = d_part[t];
    sh[t] = v;
    __syncthreads();
    for (int off = 1; off < SCB; off <<= 1) {
        int u = (t >= off) ? sh[t - off] : 0;
        __syncthreads();
        sh[t] += u;
        __syncthreads();
    }
    d_pbase[t] = sh[t] - v;
    if (t == SCB - 1) d_rs[NN] = sh[SCB - 1];
}

__global__ void __launch_bounds__(256) k_scan3() {
    __shared__ int sh[256];
    int t = threadIdx.x;
    int i0 = blockIdx.x * 1024 + t * 4;
    int s = scan_chunk_sum(i0);
    sh[t] = s;
    __syncthreads();
    for (int off = 1; off < 256; off <<= 1) {
        int u = (t >= off) ? sh[t - off] : 0;
        __syncthreads();
        sh[t] += u;
        __syncthreads();
    }
    int run = d_pbase[blockIdx.x] + sh[t] - s;
#pragma unroll
    for (int j = 0; j < 4; j++) {
        int i = i0 + j;
        if (i < NN) {
            d_rs[i] = run;
            d_cur[i] = run;
            run += d_cnt[i];
            d_cnt[i] = 0;   // self-clean for next graph replay
        }
    }
}

// ---------------- precompute folded constants (2 phases) ----------------
__global__ void __launch_bounds__(256) k_pre(const float* __restrict__ W1,
                                             const float* __restrict__ as1,
                                             const float* __restrict__ ad1,
                                             const float* __restrict__ We1,
                                             const float* __restrict__ ae1,
                                             const float* __restrict__ We2,
                                             const float* __restrict__ ae2,
                                             const float* __restrict__ b1,
                                             const float* __restrict__ W2,
                                             const float* __restrict__ as2,
                                             const float* __restrict__ ad2,
                                             const float* __restrict__ b2,
                                             const float* __restrict__ Wr1) {
    int t = threadIdx.x;
    // ---- phase A: u/v/c, bvec, G ----
    if (t < 4) {
        float s = 0;
        for (int d = 0; d < 64; d++) s += W1[t * 64 + d] * as1[t * 64 + d];
        d_u0[t] = s;
    } else if (t < 8) {
        int h = t - 4;
        float s = 0;
        for (int d = 0; d < 64; d++) s += W1[256 + h * 64 + d] * as1[h * 64 + d];
        d_u1[h] = s;
    } else if (t < 12) {
        int h = t - 8;
        float s = 0;
        for (int d = 0; d < 64; d++) s += W1[h * 64 + d] * ad1[h * 64 + d];
        d_v0[h] = s;
    } else if (t < 16) {
        int h = t - 12;
        float s = 0;
        for (int d = 0; d < 64; d++) s += W1[256 + h * 64 + d] * ad1[h * 64 + d];
        d_v1[h] = s;
    } else if (t < 20) {
        int h = t - 16;
        float s = 0;
        for (int d = 0; d < 64; d++) s += We1[h * 64 + d] * ae1[h * 64 + d];
        d_c1[h] = s;
    } else if (t == 20) {
        float s = 0;
        for (int d = 0; d < 64; d++) s += We2[d] * ae2[d];
        d_c2s = s;
    }
    if (t >= 64 && t < 128) {
        int j = t - 64;
        float s = 0;
        for (int c = 0; c < 256; c++) s += b1[c] * W2[c * 64 + j];
        d_bvec[j] = s;
    }
#pragma unroll
    for (int rep = 0; rep < 2; rep++) {
        int idx = rep * 256 + t;
        int i = idx >> 8, rem = idx & 255, h = rem >> 6, j = rem & 63;
        float s = 0;
        for (int d = 0; d < 64; d++)
            s += W1[i * 256 + h * 64 + d] * W2[(h * 64 + d) * 64 + j];
        d_G[idx] = s;
    }
    __syncthreads();   // d_G, d_bvec visible block-wide

    // ---- phase B: gA/gD, cA/cD, GW, bB2/bBV ----
#pragma unroll
    for (int rep = 0; rep < 2; rep++) {
        int idx = rep * 256 + t;     // q*64 + j
        int q = idx >> 6, j = idx & 63;
        float s = 0;
        for (int k = 0; k < 64; k++) s += d_G[q * 64 + k] * Wr1[k * 64 + j];
        d_GW[idx] = s;
    }
    if (t < 8) {
        float s = 0;
        for (int j = 0; j < 64; j++) s += d_G[t * 64 + j] * as2[j];
        d_gA[t] = s;
    } else if (t < 16) {
        int q = t - 8;
        float s = 0;
        for (int j = 0; j < 64; j++) s += d_G[q * 64 + j] * ad2[j];
        d_gD[q] = s;
    } else if (t == 16) {
        float s = 0;
        for (int j = 0; j < 64; j++) s += d_bvec[j] * as2[j];
        d_cA = s;
    } else if (t == 17) {
        float s = 0;
        for (int j = 0; j < 64; j++) s += d_bvec[j] * ad2[j];
        d_cD = s;
    }
    if (t >= 64 && t < 128) {
        int j = t - 64;
        float s = 0;
        for (int k = 0; k < 64; k++) s += b2[k] * Wr1[k * 64 + j];
        d_bB2[j] = s;
    } else if (t >= 128 && t < 192) {
        int j = t - 128;
        float s = 0;
        for (int k = 0; k < 64; k++) s += d_bvec[k] * Wr1[k * 64 + j];
        d_bBV[j] = s;
    }
}

// ---------------- fill CSR buckets (slim records) ----------------
__global__ void __launch_bounds__(256) k_fill(const int* __restrict__ ei,
                                              const float* __restrict__ attr) {
    int e = blockIdx.x * 256 + threadIdx.x;
    if (e >= NE) return;
    int s = ei[e], dd = ei[NE + e];
    if ((unsigned)s >= NN || (unsigned)dd >= NN) return;
    int pos = atomicAdd(&d_cur[dd], 1);
    if ((unsigned)pos >= NE) return;
    d_sa[pos] = make_int2(s, __float_as_int(attr[e]));
    d_eid[pos] = e;
}

// ---------------- layer-1: single-pass softmax + rank-2 agg -> S, dots -----
__global__ void __launch_bounds__(256) k_agg1(const float* __restrict__ x) {
    int warp = threadIdx.x >> 5, lane = threadIdx.x & 31;
    int n = blockIdx.x * 8 + warp;   // grid exact
    int r0 = d_rs[n], r1 = d_rs[n + 1];

    float2 xn = __ldg((const float2*)x + n);
    float adh[4], u0[4], u1[4], c1[4];
#pragma unroll
    for (int h = 0; h < 4; h++) {
        u0[h] = d_u0[h]; u1[h] = d_u1[h]; c1[h] = d_c1[h];
        adh[h] = xn.x * d_v0[h] + xn.y * d_v1[h];
    }

    float z[4] = {0, 0, 0, 0};
    float acc[8] = {0, 0, 0, 0, 0, 0, 0, 0};
    for (int pos = r0 + lane; pos < r1; pos += 32) {
        int2 p = __ldg(&d_sa[pos]);
        float a = __int_as_float(p.y);
        float2 xs = __ldg((const float2*)x + p.x);
#pragma unroll
        for (int h = 0; h < 4; h++) {
            float lg = lrelu(xs.x * u0[h] + xs.y * u1[h] + adh[h] + a * c1[h]);
            float w = __expf(lg);
            z[h] += w;
            acc[2 * h] += w * xs.x;
            acc[2 * h + 1] += w * xs.y;
        }
    }
#pragma unroll
    for (int off = 16; off; off >>= 1) {
#pragma unroll
        for (int h = 0; h < 4; h++)
            z[h] += __shfl_xor_sync(0xffffffffu, z[h], off);
#pragma unroll
        for (int q = 0; q < 8; q++)
            acc[q] += __shfl_xor_sync(0xffffffffu, acc[q], off);
    }
    if (lane == 0) {
        float rz0 = 1.f / (z[0] + 1e-16f);
        float rz1 = 1.f / (z[1] + 1e-16f);
        float rz2 = 1.f / (z[2] + 1e-16f);
        float rz3 = 1.f / (z[3] + 1e-16f);
        // q = i*4+h ordering: Sq[q] = acc[2h+i]*rz[h]
        float S0 = acc[0] * rz0, S1 = acc[2] * rz1, S2 = acc[4] * rz2, S3 = acc[6] * rz3;
        float S4 = acc[1] * rz0, S5 = acc[3] * rz1, S6 = acc[5] * rz2, S7 = acc[7] * rz3;
        float4* sp = (float4*)(d_S + (long)n * 8);
        sp[0] = make_float4(S0, S1, S2, S3);
        sp[1] = make_float4(S4, S5, S6, S7);
        d_als2[n] = d_cA + S0 * d_gA[0] + S1 * d_gA[1] + S2 * d_gA[2] + S3 * d_gA[3]
                         + S4 * d_gA[4] + S5 * d_gA[5] + S6 * d_gA[6] + S7 * d_gA[7];
        d_ald2[n] = d_cD + S0 * d_gD[0] + S1 * d_gD[1] + S2 * d_gD[2] + S3 * d_gD[3]
                         + S4 * d_gD[4] + S5 * d_gD[5] + S6 * d_gD[6] + S7 * d_gD[7];
    }
}

// ---------------- layer-2: single-pass softmax + rank-8 agg -> T -----------
__global__ void __launch_bounds__(256) k_agg2() {
    int t = threadIdx.x;
    int warp = t >> 5, lane = t & 31;
    int n = blockIdx.x * 8 + warp;   // grid exact
    int r0 = d_rs[n], r1 = d_rs[n + 1];
    float aldn = d_ald2[n];
    float c2 = d_c2s;

    float z = 0.f;
    float T[8] = {0, 0, 0, 0, 0, 0, 0, 0};
    for (int pos = r0 + lane; pos < r1; pos += 32) {
        int2 p = __ldg(&d_sa[pos]);
        float a = __int_as_float(p.y);
        float w = __expf(lrelu(__ldg(&d_als2[p.x]) + aldn + a * c2));
        const float4* sp = (const float4*)(d_S + (long)p.x * 8);
        float4 s0 = __ldg(sp), s1 = __ldg(sp + 1);
        z += w;
        T[0] += w * s0.x; T[1] += w * s0.y; T[2] += w * s0.z; T[3] += w * s0.w;
        T[4] += w * s1.x; T[5] += w * s1.y; T[6] += w * s1.z; T[7] += w * s1.w;
    }
#pragma unroll
    for (int off = 16; off; off >>= 1) {
        z += __shfl_xor_sync(0xffffffffu, z, off);
#pragma unroll
        for (int q = 0; q < 8; q++)
            T[q] += __shfl_xor_sync(0xffffffffu, T[q], off);
    }
    if (lane == 0) {
        float rz = 1.f / (z + 1e-16f);
        float4* tp = (float4*)(d_T + (long)n * 8);
        tp[0] = make_float4(T[0] * rz, T[1] * rz, T[2] * rz, T[3] * rz);
        tp[1] = make_float4(T[4] * rz, T[5] * rz, T[6] * rz, T[7] * rz);
        d_Ts[n] = (r1 > r0) ? 1.f : 0.f;
    }
}

// ---------------- gv[n] = bB2 + s*bBV + T[n]@GW ----------------
__global__ void __launch_bounds__(256) k_gemmT() {
    __shared__ float shGW[512];
    __shared__ float shB2[64], shBV[64];
    int t = threadIdx.x;
    shGW[t] = d_GW[t];
    shGW[256 + t] = d_GW[256 + t];
    if (t < 64) { shB2[t] = d_bB2[t]; shBV[t] = d_bBV[t]; }
    __syncthreads();

    int r = t & 63, cg = t >> 6;
    int n = blockIdx.x * 64 + r;
    if (n >= NN) return;
    int j0 = cg * 16;
    const float4* tp = (const float4*)(d_T + (long)n * 8);
    float4 t0 = __ldg(tp), t1 = __ldg(tp + 1);
    float Tq[8] = {t0.x, t0.y, t0.z, t0.w, t1.x, t1.y, t1.z, t1.w};
    float s = d_Ts[n];
    float o[16];
#pragma unroll
    for (int j = 0; j < 16; j++) {
        float v = shB2[j0 + j] + s * shBV[j0 + j];
#pragma unroll
        for (int q = 0; q < 8; q++) v += Tq[q] * shGW[q * 64 + j0 + j];
        o[j] = v;
    }
    float4* gp = (float4*)(d_gv + (long)n * 64 + j0);
    gp[0] = make_float4(o[0], o[1], o[2], o[3]);
    gp[1] = make_float4(o[4], o[5], o[6], o[7]);
    gp[2] = make_float4(o[8], o[9], o[10], o[11]);
    gp[3] = make_float4(o[12], o[13], o[14], o[15]);
}

// ---------------- final edge regressor (warp per dst node) ----------------
__global__ void __launch_bounds__(256) k_edge(const float* __restrict__ br1,
                                              const float* __restrict__ Wr2,
                                              const float* __restrict__ br2,
                                              float* __restrict__ out) {
    int warp = threadIdx.x >> 5, lane = threadIdx.x & 31;
    int n = blockIdx.x * 8 + warp;   // grid exact
    int r0 = d_rs[n], r1 = d_rs[n + 1];
    if (r0 >= r1) return;
    int c0 = lane * 2;
    float2 gd = *(const float2*)(d_gv + (long)n * 64 + c0);
    float2 rb = __ldg((const float2*)(br1 + c0));
    float2 w2 = __ldg((const float2*)(Wr2 + c0));
    float base0 = gd.x + rb.x, base1 = gd.y + rb.y;
    float brv = __ldg(br2);

    for (int pos = r0; pos < r1; pos += 2) {
        int sA = __ldg(&d_sa[pos]).x;
        float2 ga = *(const float2*)(d_gv + (long)sA * 64 + c0);
        float pa = fmaxf(ga.x + base0, 0.f) * w2.x + fmaxf(ga.y + base1, 0.f) * w2.y;
        bool hasB = (pos + 1) < r1;
        float pb = 0.f;
        if (hasB) {
            int sB = __ldg(&d_sa[pos + 1]).x;
            float2 gb = *(const float2*)(d_gv + (long)sB * 64 + c0);
            pb = fmaxf(gb.x + base0, 0.f) * w2.x + fmaxf(gb.y + base1, 0.f) * w2.y;
        }
#pragma unroll
        for (int off = 16; off; off >>= 1) {
            pa += __shfl_xor_sync(0xffffffffu, pa, off);
            pb += __shfl_xor_sync(0xffffffffu, pb, off);
        }
        if (lane == 0) out[__ldg(&d_eid[pos])] = pa + brv;
        if (hasB && lane == 1) out[__ldg(&d_eid[pos + 1])] = pb + brv;
    }
}

// ---------------- host diagnostics (static; no allocation) -----------------
static int   h_rs[1];
static float h_S[2], h_gv[2], h_out[8];

// ---------------- launch ----------------
extern "C" void kernel_launch(void* const* d_in, const int* in_sizes, int n_in,
                              void* d_out, int out_size) {
    const float* x    = (const float*)d_in[0];
    const int*   ei   = (const int*)d_in[1];
    const float* attr = (const float*)d_in[2];
    const float* W1   = (const float*)d_in[3];
    const float* We1  = (const float*)d_in[4];
    const float* as1  = (const float*)d_in[5];
    const float* ad1  = (const float*)d_in[6];
    const float* ae1  = (const float*)d_in[7];
    const float* b1   = (const float*)d_in[8];
    const float* W2   = (const float*)d_in[9];
    const float* We2  = (const float*)d_in[10];
    const float* as2  = (const float*)d_in[11];
    const float* ad2  = (const float*)d_in[12];
    const float* ae2  = (const float*)d_in[13];
    const float* b2   = (const float*)d_in[14];
    const float* Wr1  = (const float*)d_in[15];
    const float* br1  = (const float*)d_in[16];
    const float* Wr2  = (const float*)d_in[17];
    const float* br2  = (const float*)d_in[18];
    float* out = (float*)d_out;

    const int EB = (NE + 255) / 256;
    const int NB8 = (NN + 7) / 8;     // 12500 exact
    const int NB64 = (NN + 63) / 64;

    k_count<<<EB, 256>>>(ei);
    k_pre<<<1, 256>>>(W1, as1, ad1, We1, ae1, We2, ae2, b1, W2, as2, ad2, b2, Wr1);
    k_scan1<<<SCB, 256>>>();
    k_scan2<<<1, SCB>>>();
    k_scan3<<<SCB, 256>>>();
    k_fill<<<EB, 256>>>(ei, attr);
    k_agg1<<<NB8, 256>>>(x);
    k_agg2<<<NB8, 256>>>();
    k_gemmT<<<NB64, 256>>>();
    k_edge<<<NB8, 256>>>(br1, Wr2, br2, out);

    // -------- slim health check: only on the non-capture correctness call --
    cudaStreamCaptureStatus cs = cudaStreamCaptureStatusNone;
    cudaStreamIsCapturing((cudaStream_t)0, &cs);
    if (cs != cudaStreamCaptureStatusNone) return;

    h_rs[0] = -777;
    cudaMemcpyFromSymbolAsync(h_rs, d_rs, 4, (size_t)NN * 4, cudaMemcpyDeviceToHost, 0);
    cudaMemcpyFromSymbolAsync(h_S, d_S, 8, 0, cudaMemcpyDeviceToHost, 0);
    cudaMemcpyFromSymbolAsync(h_gv, d_gv, 8, 0, cudaMemcpyDeviceToHost, 0);
    cudaMemcpyAsync(h_out, out, 32, cudaMemcpyDeviceToHost, 0);
    cudaError_t sticky = cudaGetLastError();

    float omax = 0.f;
    bool ofin = true;
    for (int i = 0; i < 8; i++) {
        if (!isfinite(h_out[i])) ofin = false;
        float a = fabsf(h_out[i]);
        if (a > omax) omax = a;
    }
    bool healthy = sticky == cudaSuccess && h_rs[0] == NE && ofin &&
                   omax > 1e-30f &&
                   (fabsf(h_gv[0]) + fabsf(h_gv[1])) > 0.f;
    if (healthy) return;

    for (int pass = 0; pass < 2; pass++) {
        FILE* f = pass ? stderr : stdout;
        fprintf(f, "DG sticky=%d(%s) rsN=%d S=[%g %g] gv=[%g %g] out=[%g %g %g %g]\n",
                (int)sticky, cudaGetErrorString(sticky), h_rs[0],
                h_S[0], h_S[1], h_gv[0], h_gv[1],
                h_out[0], h_out[1], h_out[2], h_out[3]);
        fflush(f);
    }
    abort();
}

// round 15
// speedup vs baseline: 1.8889x; 1.0345x over previous
#include <cuda_runtime.h>
#include <cstdio>
#include <cstdlib>
#include <math.h>

#define NN 100000
#define NE 1600000
#define NEGS 0.2f
#define SCB 128   // scan blocks (128*256*4 = 131072 >= NN)

// ---------------- scratch (device globals; zero-init at load) --------------
__device__ __align__(16) int   d_cnt[NN];     // re-zeroed by k_scan3 each run
__device__ __align__(16) int   d_rs[NN + 1];
__device__ __align__(16) int   d_cur[NN];
__device__ __align__(16) int   d_part[SCB];
__device__ __align__(16) int2  d_sa[NE];      // {src, attr-bits}, dst-sorted
__device__ __align__(16) int   d_eid[NE];     // original edge id, dst-sorted
__device__ __align__(16) float d_S[NN * 8];   // layer-1 per-node aggregates (q=i*4+h)
__device__ __align__(16) float d_T[NN * 8];   // layer-2 per-node aggregates
__device__ __align__(16) float d_Ts[NN];      // 1 if node has incoming edges
__device__ __align__(16) float d_als2[NN];
__device__ __align__(16) float d_ald2[NN];
__device__ __align__(16) float d_gv[NN * 64];
// folded constants
__device__ __align__(16) float d_u0[4], d_u1[4];
__device__ __align__(16) float d_v0[4], d_v1[4];
__device__ __align__(16) float d_c1[4];
__device__ float d_c2s;
__device__ __align__(16) float d_G[512];      // [q][j], q = i*4+h
__device__ __align__(16) float d_bvec[64];    // b1 @ W2
__device__ __align__(16) float d_gA[8], d_gD[8];   // G @ as2, G @ ad2
__device__ float d_cA, d_cD;                       // bvec·as2, bvec·ad2
__device__ __align__(16) float d_GW[512];     // [q][j] = G[q,:] @ Wr1
__device__ __align__(16) float d_bB2[64];     // b2 @ Wr1
__device__ __align__(16) float d_bBV[64];     // bvec @ Wr1

__device__ __forceinline__ float lrelu(float x) { return x > 0.f ? x : NEGS * x; }

// ---------------- CSR build ----------------
__global__ void __launch_bounds__(256) k_count(const int* __restrict__ ei) {
    int e = blockIdx.x * 256 + threadIdx.x;
    if (e < NE) {
        int d = ei[NE + e];
        if ((unsigned)d < NN) atomicAdd(&d_cnt[d], 1);
    }
}

__device__ __forceinline__ int scan_chunk_sum(int i0) {
    int s = 0;
#pragma unroll
    for (int j = 0; j < 4; j++) {
        int i = i0 + j;
        if (i < NN) s += d_cnt[i];
    }
    return s;
}

__global__ void __launch_bounds__(256) k_scan1() {
    __shared__ int sh[256];
    int t = threadIdx.x;
    int i0 = blockIdx.x * 1024 + t * 4;
    sh[t] = scan_chunk_sum(i0);
    __syncthreads();
    for (int off = 128; off; off >>= 1) {
        if (t < off) sh[t] += sh[t + off];
        __syncthreads();
    }
    if (t == 0) d_part[blockIdx.x] = sh[0];
}

// scan of partials folded in: every block re-scans the 128 partials itself
__global__ void __launch_bounds__(256) k_scan3() {
    __shared__ int sh[256];
    __shared__ int shp[SCB];
    int t = threadIdx.x;
    if (t < SCB) shp[t] = d_part[t];
    __syncthreads();
    for (int off = 1; off < SCB; off <<= 1) {
        int u = (t >= off && t < SCB) ? shp[t - off] : 0;
        __syncthreads();
        if (t < SCB) shp[t] += u;
        __syncthreads();
    }
    int i0 = blockIdx.x * 1024 + t * 4;
    int s = scan_chunk_sum(i0);
    sh[t] = s;
    __syncthreads();
    for (int off = 1; off < 256; off <<= 1) {
        int u = (t >= off) ? sh[t - off] : 0;
        __syncthreads();
        sh[t] += u;
        __syncthreads();
    }
    int bbase = (blockIdx.x == 0) ? 0 : shp[blockIdx.x - 1];
    int run = bbase + sh[t] - s;
#pragma unroll
    for (int j = 0; j < 4; j++) {
        int i = i0 + j;
        if (i < NN) {
            d_rs[i] = run;
            d_cur[i] = run;
            run += d_cnt[i];
            d_cnt[i] = 0;   // self-clean for next graph replay
        }
    }
    if (blockIdx.x == 0 && t == 0) d_rs[NN] = shp[SCB - 1];
}

// ---------------- precompute folded constants (2 phases) ----------------
__global__ void __launch_bounds__(256) k_pre(const float* __restrict__ W1,
                                             const float* __restrict__ as1,
                                             const float* __restrict__ ad1,
                                             const float* __restrict__ We1,
                                             const float* __restrict__ ae1,
                                             const float* __restrict__ We2,
                                             const float* __restrict__ ae2,
                                             const float* __restrict__ b1,
                                             const float* __restrict__ W2,
                                             const float* __restrict__ as2,
                                             const float* __restrict__ ad2,
                                             const float* __restrict__ b2,
                                             const float* __restrict__ Wr1) {
    int t = threadIdx.x;
    if (t < 4) {
        float s = 0;
        for (int d = 0; d < 64; d++) s += W1[t * 64 + d] * as1[t * 64 + d];
        d_u0[t] = s;
    } else if (t < 8) {
        int h = t - 4;
        float s = 0;
        for (int d = 0; d < 64; d++) s += W1[256 + h * 64 + d] * as1[h * 64 + d];
        d_u1[h] = s;
    } else if (t < 12) {
        int h = t - 8;
        float s = 0;
        for (int d = 0; d < 64; d++) s += W1[h * 64 + d] * ad1[h * 64 + d];
        d_v0[h] = s;
    } else if (t < 16) {
        int h = t - 12;
        float s = 0;
        for (int d = 0; d < 64; d++) s += W1[256 + h * 64 + d] * ad1[h * 64 + d];
        d_v1[h] = s;
    } else if (t < 20) {
        int h = t - 16;
        float s = 0;
        for (int d = 0; d < 64; d++) s += We1[h * 64 + d] * ae1[h * 64 + d];
        d_c1[h] = s;
    } else if (t == 20) {
        float s = 0;
        for (int d = 0; d < 64; d++) s += We2[d] * ae2[d];
        d_c2s = s;
    }
    if (t >= 64 && t < 128) {
        int j = t - 64;
        float s = 0;
        for (int c = 0; c < 256; c++) s += b1[c] * W2[c * 64 + j];
        d_bvec[j] = s;
    }
#pragma unroll
    for (int rep = 0; rep < 2; rep++) {
        int idx = rep * 256 + t;
        int i = idx >> 8, rem = idx & 255, h = rem >> 6, j = rem & 63;
        float s = 0;
        for (int d = 0; d < 64; d++)
            s += W1[i * 256 + h * 64 + d] * W2[(h * 64 + d) * 64 + j];
        d_G[idx] = s;
    }
    __syncthreads();

#pragma unroll
    for (int rep = 0; rep < 2; rep++) {
        int idx = rep * 256 + t;     // q*64 + j
        int q = idx >> 6, j = idx & 63;
        float s = 0;
        for (int k = 0; k < 64; k++) s += d_G[q * 64 + k] * Wr1[k * 64 + j];
        d_GW[idx] = s;
    }
    if (t < 8) {
        float s = 0;
        for (int j = 0; j < 64; j++) s += d_G[t * 64 + j] * as2[j];
        d_gA[t] = s;
    } else if (t < 16) {
        int q = t - 8;
        float s = 0;
        for (int j = 0; j < 64; j++) s += d_G[q * 64 + j] * ad2[j];
        d_gD[q] = s;
    } else if (t == 16) {
        float s = 0;
        for (int j = 0; j < 64; j++) s += d_bvec[j] * as2[j];
        d_cA = s;
    } else if (t == 17) {
        float s = 0;
        for (int j = 0; j < 64; j++) s += d_bvec[j] * ad2[j];
        d_cD = s;
    }
    if (t >= 64 && t < 128) {
        int j = t - 64;
        float s = 0;
        for (int k = 0; k < 64; k++) s += b2[k] * Wr1[k * 64 + j];
        d_bB2[j] = s;
    } else if (t >= 128 && t < 192) {
        int j = t - 128;
        float s = 0;
        for (int k = 0; k < 64; k++) s += d_bvec[k] * Wr1[k * 64 + j];
        d_bBV[j] = s;
    }
}

// ---------------- fill CSR buckets (slim records) ----------------
__global__ void __launch_bounds__(256) k_fill(const int* __restrict__ ei,
                                              const float* __restrict__ attr) {
    int e = blockIdx.x * 256 + threadIdx.x;
    if (e >= NE) return;
    int s = ei[e], dd = ei[NE + e];
    if ((unsigned)s >= NN || (unsigned)dd >= NN) return;
    int pos = atomicAdd(&d_cur[dd], 1);
    if ((unsigned)pos >= NE) return;
    d_sa[pos] = make_int2(s, __float_as_int(attr[e]));
    d_eid[pos] = e;
}

// ---------------- layer-1: single-pass softmax + rank-2 agg -> S, dots -----
__global__ void __launch_bounds__(256) k_agg1(const float* __restrict__ x) {
    int warp = threadIdx.x >> 5, lane = threadIdx.x & 31;
    int n = blockIdx.x * 8 + warp;   // grid exact
    int r0 = d_rs[n], r1 = d_rs[n + 1];

    float2 xn = __ldg((const float2*)x + n);
    float adh[4], u0[4], u1[4], c1[4];
#pragma unroll
    for (int h = 0; h < 4; h++) {
        u0[h] = d_u0[h]; u1[h] = d_u1[h]; c1[h] = d_c1[h];
        adh[h] = xn.x * d_v0[h] + xn.y * d_v1[h];
    }

    float z[4] = {0, 0, 0, 0};
    float acc[8] = {0, 0, 0, 0, 0, 0, 0, 0};
    for (int pos = r0 + lane; pos < r1; pos += 32) {
        int2 p = __ldg(&d_sa[pos]);
        float a = __int_as_float(p.y);
        float2 xs = __ldg((const float2*)x + p.x);
#pragma unroll
        for (int h = 0; h < 4; h++) {
            float lg = lrelu(xs.x * u0[h] + xs.y * u1[h] + adh[h] + a * c1[h]);
            float w = __expf(lg);
            z[h] += w;
            acc[2 * h] += w * xs.x;
            acc[2 * h + 1] += w * xs.y;
        }
    }
#pragma unroll
    for (int off = 16; off; off >>= 1) {
#pragma unroll
        for (int h = 0; h < 4; h++)
            z[h] += __shfl_xor_sync(0xffffffffu, z[h], off);
#pragma unroll
        for (int q = 0; q < 8; q++)
            acc[q] += __shfl_xor_sync(0xffffffffu, acc[q], off);
    }
    if (lane == 0) {
        float rz0 = 1.f / (z[0] + 1e-16f);
        float rz1 = 1.f / (z[1] + 1e-16f);
        float rz2 = 1.f / (z[2] + 1e-16f);
        float rz3 = 1.f / (z[3] + 1e-16f);
        float S0 = acc[0] * rz0, S1 = acc[2] * rz1, S2 = acc[4] * rz2, S3 = acc[6] * rz3;
        float S4 = acc[1] * rz0, S5 = acc[3] * rz1, S6 = acc[5] * rz2, S7 = acc[7] * rz3;
        float4* sp = (float4*)(d_S + (long)n * 8);
        sp[0] = make_float4(S0, S1, S2, S3);
        sp[1] = make_float4(S4, S5, S6, S7);
        d_als2[n] = d_cA + S0 * d_gA[0] + S1 * d_gA[1] + S2 * d_gA[2] + S3 * d_gA[3]
                         + S4 * d_gA[4] + S5 * d_gA[5] + S6 * d_gA[6] + S7 * d_gA[7];
        d_ald2[n] = d_cD + S0 * d_gD[0] + S1 * d_gD[1] + S2 * d_gD[2] + S3 * d_gD[3]
                         + S4 * d_gD[4] + S5 * d_gD[5] + S6 * d_gD[6] + S7 * d_gD[7];
    }
}

// ---------------- layer-2: single-pass softmax + rank-8 agg -> T -----------
__global__ void __launch_bounds__(256) k_agg2() {
    int t = threadIdx.x;
    int warp = t >> 5, lane = t & 31;
    int n = blockIdx.x * 8 + warp;   // grid exact
    int r0 = d_rs[n], r1 = d_rs[n + 1];
    float aldn = d_ald2[n];
    float c2 = d_c2s;

    float z = 0.f;
    float T[8] = {0, 0, 0, 0, 0, 0, 0, 0};
    for (int pos = r0 + lane; pos < r1; pos += 32) {
        int2 p = __ldg(&d_sa[pos]);
        float a = __int_as_float(p.y);
        float w = __expf(lrelu(__ldg(&d_als2[p.x]) + aldn + a * c2));
        const float4* sp = (const float4*)(d_S + (long)p.x * 8);
        float4 s0 = __ldg(sp), s1 = __ldg(sp + 1);
        z += w;
        T[0] += w * s0.x; T[1] += w * s0.y; T[2] += w * s0.z; T[3] += w * s0.w;
        T[4] += w * s1.x; T[5] += w * s1.y; T[6] += w * s1.z; T[7] += w * s1.w;
    }
#pragma unroll
    for (int off = 16; off; off >>= 1) {
        z += __shfl_xor_sync(0xffffffffu, z, off);
#pragma unroll
        for (int q = 0; q < 8; q++)
            T[q] += __shfl_xor_sync(0xffffffffu, T[q], off);
    }
    if (lane == 0) {
        float rz = 1.f / (z + 1e-16f);
        float4* tp = (float4*)(d_T + (long)n * 8);
        tp[0] = make_float4(T[0] * rz, T[1] * rz, T[2] * rz, T[3] * rz);
        tp[1] = make_float4(T[4] * rz, T[5] * rz, T[6] * rz, T[7] * rz);
        d_Ts[n] = (r1 > r0) ? 1.f : 0.f;
    }
}

// ---------------- gv[n] = bB2 + s*bBV + T[n]@GW ----------------
__global__ void __launch_bounds__(256) k_gemmT() {
    __shared__ float shGW[512];
    __shared__ float shB2[64], shBV[64];
    int t = threadIdx.x;
    shGW[t] = d_GW[t];
    shGW[256 + t] = d_GW[256 + t];
    if (t < 64) { shB2[t] = d_bB2[t]; shBV[t] = d_bBV[t]; }
    __syncthreads();

    int r = t & 63, cg = t >> 6;
    int n = blockIdx.x * 64 + r;
    if (n >= NN) return;
    int j0 = cg * 16;
    const float4* tp = (const float4*)(d_T + (long)n * 8);
    float4 t0 = __ldg(tp), t1 = __ldg(tp + 1);
    float Tq[8] = {t0.x, t0.y, t0.z, t0.w, t1.x, t1.y, t1.z, t1.w};
    float s = d_Ts[n];
    float o[16];
#pragma unroll
    for (int j = 0; j < 16; j++) {
        float v = shB2[j0 + j] + s * shBV[j0 + j];
#pragma unroll
        for (int q = 0; q < 8; q++) v += Tq[q] * shGW[q * 64 + j0 + j];
        o[j] = v;
    }
    float4* gp = (float4*)(d_gv + (long)n * 64 + j0);
    gp[0] = make_float4(o[0], o[1], o[2], o[3]);
    gp[1] = make_float4(o[4], o[5], o[6], o[7]);
    gp[2] = make_float4(o[8], o[9], o[10], o[11]);
    gp[3] = make_float4(o[12], o[13], o[14], o[15]);
}

// ---------------- final edge regressor (warp per node; 4 edges parallel) ---
__global__ void __launch_bounds__(256) k_edge(const float* __restrict__ br1,
                                              const float* __restrict__ Wr2,
                                              const float* __restrict__ br2,
                                              float* __restrict__ out) {
    int warp = threadIdx.x >> 5, lane = threadIdx.x & 31;
    int n = blockIdx.x * 8 + warp;   // grid exact
    int r0 = d_rs[n], r1 = d_rs[n + 1];
    if (r0 >= r1) return;
    int g = lane >> 3;        // edge slot 0-3
    int l8 = lane & 7;        // dim octet
    int c0 = l8 * 8;
    // base[8] = gv[n][c0..c0+7] + br1, weights w2[8]
    const float4* gn = (const float4*)(d_gv + (long)n * 64 + c0);
    float4 b0 = gn[0], b1 = gn[1];
    float4 q0 = __ldg((const float4*)(br1 + c0)), q1 = __ldg((const float4*)(br1 + c0 + 4));
    b0.x += q0.x; b0.y += q0.y; b0.z += q0.z; b0.w += q0.w;
    b1.x += q1.x; b1.y += q1.y; b1.z += q1.z; b1.w += q1.w;
    float4 w0 = __ldg((const float4*)(Wr2 + c0)), w1 = __ldg((const float4*)(Wr2 + c0 + 4));
    float brv = __ldg(br2);

    for (int pos0 = r0; pos0 < r1; pos0 += 4) {
        int pos = pos0 + g;
        bool act = pos < r1;
        float p = 0.f;
        int eid = 0;
        if (act) {
            int s = __ldg(&d_sa[pos]).x;
            const float4* gs = (const float4*)(d_gv + (long)s * 64 + c0);
            float4 a0 = __ldg(gs), a1 = __ldg(gs + 1);
            p += fmaxf(a0.x + b0.x, 0.f) * w0.x;
            p += fmaxf(a0.y + b0.y, 0.f) * w0.y;
            p += fmaxf(a0.z + b0.z, 0.f) * w0.z;
            p += fmaxf(a0.w + b0.w, 0.f) * w0.w;
            p += fmaxf(a1.x + b1.x, 0.f) * w1.x;
            p += fmaxf(a1.y + b1.y, 0.f) * w1.y;
            p += fmaxf(a1.z + b1.z, 0.f) * w1.z;
            p += fmaxf(a1.w + b1.w, 0.f) * w1.w;
            eid = __ldg(&d_eid[pos]);
        }
#pragma unroll
        for (int off = 4; off; off >>= 1)
            p += __shfl_xor_sync(0xffffffffu, p, off);
        if (act && l8 == 0) out[eid] = p + brv;
    }
}

// ---------------- host diagnostics (static; no allocation) -----------------
static int   h_rs[1];
static float h_S[2], h_gv[2], h_out[8];

// ---------------- launch ----------------
extern "C" void kernel_launch(void* const* d_in, const int* in_sizes, int n_in,
                              void* d_out, int out_size) {
    const float* x    = (const float*)d_in[0];
    const int*   ei   = (const int*)d_in[1];
    const float* attr = (const float*)d_in[2];
    const float* W1   = (const float*)d_in[3];
    const float* We1  = (const float*)d_in[4];
    const float* as1  = (const float*)d_in[5];
    const float* ad1  = (const float*)d_in[6];
    const float* ae1  = (const float*)d_in[7];
    const float* b1   = (const float*)d_in[8];
    const float* W2   = (const float*)d_in[9];
    const float* We2  = (const float*)d_in[10];
    const float* as2  = (const float*)d_in[11];
    const float* ad2  = (const float*)d_in[12];
    const float* ae2  = (const float*)d_in[13];
    const float* b2   = (const float*)d_in[14];
    const float* Wr1  = (const float*)d_in[15];
    const float* br1  = (const float*)d_in[16];
    const float* Wr2  = (const float*)d_in[17];
    const float* br2  = (const float*)d_in[18];
    float* out = (float*)d_out;

    const int EB = (NE + 255) / 256;
    const int NB8 = (NN + 7) / 8;     // 12500 exact
    const int NB64 = (NN + 63) / 64;

    k_count<<<EB, 256>>>(ei);
    k_pre<<<1, 256>>>(W1, as1, ad1, We1, ae1, We2, ae2, b1, W2, as2, ad2, b2, Wr1);
    k_scan1<<<SCB, 256>>>();
    k_scan3<<<SCB, 256>>>();
    k_fill<<<EB, 256>>>(ei, attr);
    k_agg1<<<NB8, 256>>>(x);
    k_agg2<<<NB8, 256>>>();
    k_gemmT<<<NB64, 256>>>();
    k_edge<<<NB8, 256>>>(br1, Wr2, br2, out);

    // -------- slim health check: only on the non-capture correctness call --
    cudaStreamCaptureStatus cs = cudaStreamCaptureStatusNone;
    cudaStreamIsCapturing((cudaStream_t)0, &cs);
    if (cs != cudaStreamCaptureStatusNone) return;

    h_rs[0] = -777;
    cudaMemcpyFromSymbolAsync(h_rs, d_rs, 4, (size_t)NN * 4, cudaMemcpyDeviceToHost, 0);
    cudaMemcpyFromSymbolAsync(h_S, d_S, 8, 0, cudaMemcpyDeviceToHost, 0);
    cudaMemcpyFromSymbolAsync(h_gv, d_gv, 8, 0, cudaMemcpyDeviceToHost, 0);
    cudaMemcpyAsync(h_out, out, 32, cudaMemcpyDeviceToHost, 0);
    cudaError_t sticky = cudaGetLastError();

    float omax = 0.f;
    bool ofin = true;
    for (int i = 0; i < 8; i++) {
        if (!isfinite(h_out[i])) ofin = false;
        float a = fabsf(h_out[i]);
        if (a > omax) omax = a;
    }
    bool healthy = sticky == cudaSuccess && h_rs[0] == NE && ofin &&
                   omax > 1e-30f &&
                   (fabsf(h_gv[0]) + fabsf(h_gv[1])) > 0.f;
    if (healthy) return;

    for (int pass = 0; pass < 2; pass++) {
        FILE* f = pass ? stderr : stdout;
        fprintf(f, "DG sticky=%d(%s) rsN=%d S=[%g %g] gv=[%g %g] out=[%g %g %g %g]\n",
                (int)sticky, cudaGetErrorString(sticky), h_rs[0],
                h_S[0], h_S[1], h_gv[0], h_gv[1],
                h_out[0], h_out[1], h_out[2], h_out[3]);
        fflush(f);
    }
    abort();
}

// round 16
// speedup vs baseline: 1.9104x; 1.0114x over previous
#include <cuda_runtime.h>
#include <cstdio>
#include <cstdlib>
#include <math.h>

#define NN 100000
#define NE 1600000
#define NEGS 0.2f
#define SCB 128   // scan blocks (128*256*4 = 131072 >= NN)
#define EB 6250   // edge blocks (NE/256)

// ---------------- scratch (device globals; zero-init at load) --------------
__device__ __align__(16) int   d_cnt[NN];     // re-zeroed by k_scan3 each run
__device__ __align__(16) int   d_rs[NN + 1];
__device__ __align__(16) int   d_cur[NN];
__device__ __align__(16) int   d_part[SCB];
__device__ __align__(16) int2  d_sa[NE];      // {src, attr-bits}, dst-sorted
__device__ __align__(16) int   d_eid[NE];     // original edge id, dst-sorted
__device__ __align__(16) float d_S[NN * 8];   // layer-1 per-node aggregates (q=i*4+h)
__device__ __align__(16) float d_als2[NN];
__device__ __align__(16) float d_ald2[NN];
__device__ __align__(16) float d_gv[NN * 64];
// folded constants
__device__ __align__(16) float d_u0[4], d_u1[4];
__device__ __align__(16) float d_v0[4], d_v1[4];
__device__ __align__(16) float d_c1[4];
__device__ float d_c2s;
__device__ __align__(16) float d_G[512];      // [q][j], q = i*4+h
__device__ __align__(16) float d_bvec[64];    // b1 @ W2
__device__ __align__(16) float d_gA[8], d_gD[8];   // G @ as2, G @ ad2
__device__ float d_cA, d_cD;                       // bvec·as2, bvec·ad2
__device__ __align__(16) float d_GW[512];     // [q][j] = G[q,:] @ Wr1
__device__ __align__(16) float d_bB2[64];     // b2 @ Wr1
__device__ __align__(16) float d_bBV[64];     // bvec @ Wr1

__device__ __forceinline__ float lrelu(float x) { return x > 0.f ? x : NEGS * x; }

// ---------------- count + folded-constant precompute (fused launch) --------
__global__ void __launch_bounds__(256) k_count_pre(const int* __restrict__ ei,
                                                   const float* __restrict__ W1,
                                                   const float* __restrict__ as1,
                                                   const float* __restrict__ ad1,
                                                   const float* __restrict__ We1,
                                                   const float* __restrict__ ae1,
                                                   const float* __restrict__ We2,
                                                   const float* __restrict__ ae2,
                                                   const float* __restrict__ b1,
                                                   const float* __restrict__ W2,
                                                   const float* __restrict__ as2,
                                                   const float* __restrict__ ad2,
                                                   const float* __restrict__ b2,
                                                   const float* __restrict__ Wr1) {
    if (blockIdx.x < EB) {
        int e = blockIdx.x * 256 + threadIdx.x;
        if (e < NE) {
            int d = ei[NE + e];
            if ((unsigned)d < NN) atomicAdd(&d_cnt[d], 1);
        }
        return;
    }
    // ---- precompute block ----
    int t = threadIdx.x;
    if (t < 4) {
        float s = 0;
        for (int d = 0; d < 64; d++) s += W1[t * 64 + d] * as1[t * 64 + d];
        d_u0[t] = s;
    } else if (t < 8) {
        int h = t - 4;
        float s = 0;
        for (int d = 0; d < 64; d++) s += W1[256 + h * 64 + d] * as1[h * 64 + d];
        d_u1[h] = s;
    } else if (t < 12) {
        int h = t - 8;
        float s = 0;
        for (int d = 0; d < 64; d++) s += W1[h * 64 + d] * ad1[h * 64 + d];
        d_v0[h] = s;
    } else if (t < 16) {
        int h = t - 12;
        float s = 0;
        for (int d = 0; d < 64; d++) s += W1[256 + h * 64 + d] * ad1[h * 64 + d];
        d_v1[h] = s;
    } else if (t < 20) {
        int h = t - 16;
        float s = 0;
        for (int d = 0; d < 64; d++) s += We1[h * 64 + d] * ae1[h * 64 + d];
        d_c1[h] = s;
    } else if (t == 20) {
        float s = 0;
        for (int d = 0; d < 64; d++) s += We2[d] * ae2[d];
        d_c2s = s;
    }
    if (t >= 64 && t < 128) {
        int j = t - 64;
        float s = 0;
        for (int c = 0; c < 256; c++) s += b1[c] * W2[c * 64 + j];
        d_bvec[j] = s;
    }
#pragma unroll
    for (int rep = 0; rep < 2; rep++) {
        int idx = rep * 256 + t;
        int i = idx >> 8, rem = idx & 255, h = rem >> 6, j = rem & 63;
        float s = 0;
        for (int d = 0; d < 64; d++)
            s += W1[i * 256 + h * 64 + d] * W2[(h * 64 + d) * 64 + j];
        d_G[idx] = s;
    }
    __syncthreads();

#pragma unroll
    for (int rep = 0; rep < 2; rep++) {
        int idx = rep * 256 + t;     // q*64 + j
        int q = idx >> 6, j = idx & 63;
        float s = 0;
        for (int k = 0; k < 64; k++) s += d_G[q * 64 + k] * Wr1[k * 64 + j];
        d_GW[idx] = s;
    }
    if (t < 8) {
        float s = 0;
        for (int j = 0; j < 64; j++) s += d_G[t * 64 + j] * as2[j];
        d_gA[t] = s;
    } else if (t < 16) {
        int q = t - 8;
        float s = 0;
        for (int j = 0; j < 64; j++) s += d_G[q * 64 + j] * ad2[j];
        d_gD[q] = s;
    } else if (t == 16) {
        float s = 0;
        for (int j = 0; j < 64; j++) s += d_bvec[j] * as2[j];
        d_cA = s;
    } else if (t == 17) {
        float s = 0;
        for (int j = 0; j < 64; j++) s += d_bvec[j] * ad2[j];
        d_cD = s;
    }
    if (t >= 64 && t < 128) {
        int j = t - 64;
        float s = 0;
        for (int k = 0; k < 64; k++) s += b2[k] * Wr1[k * 64 + j];
        d_bB2[j] = s;
    } else if (t >= 128 && t < 192) {
        int j = t - 128;
        float s = 0;
        for (int k = 0; k < 64; k++) s += d_bvec[k] * Wr1[k * 64 + j];
        d_bBV[j] = s;
    }
}

__device__ __forceinline__ int scan_chunk_sum(int i0) {
    int s = 0;
#pragma unroll
    for (int j = 0; j < 4; j++) {
        int i = i0 + j;
        if (i < NN) s += d_cnt[i];
    }
    return s;
}

__global__ void __launch_bounds__(256) k_scan1() {
    __shared__ int sh[256];
    int t = threadIdx.x;
    int i0 = blockIdx.x * 1024 + t * 4;
    sh[t] = scan_chunk_sum(i0);
    __syncthreads();
    for (int off = 128; off; off >>= 1) {
        if (t < off) sh[t] += sh[t + off];
        __syncthreads();
    }
    if (t == 0) d_part[blockIdx.x] = sh[0];
}

// scan of partials folded in: every block re-scans the 128 partials itself
__global__ void __launch_bounds__(256) k_scan3() {
    __shared__ int sh[256];
    __shared__ int shp[SCB];
    int t = threadIdx.x;
    if (t < SCB) shp[t] = d_part[t];
    __syncthreads();
    for (int off = 1; off < SCB; off <<= 1) {
        int u = (t >= off && t < SCB) ? shp[t - off] : 0;
        __syncthreads();
        if (t < SCB) shp[t] += u;
        __syncthreads();
    }
    int i0 = blockIdx.x * 1024 + t * 4;
    int s = scan_chunk_sum(i0);
    sh[t] = s;
    __syncthreads();
    for (int off = 1; off < 256; off <<= 1) {
        int u = (t >= off) ? sh[t - off] : 0;
        __syncthreads();
        sh[t] += u;
        __syncthreads();
    }
    int bbase = (blockIdx.x == 0) ? 0 : shp[blockIdx.x - 1];
    int run = bbase + sh[t] - s;
#pragma unroll
    for (int j = 0; j < 4; j++) {
        int i = i0 + j;
        if (i < NN) {
            d_rs[i] = run;
            d_cur[i] = run;
            run += d_cnt[i];
            d_cnt[i] = 0;   // self-clean for next graph replay
        }
    }
    if (blockIdx.x == 0 && t == 0) d_rs[NN] = shp[SCB - 1];
}

// ---------------- fill CSR buckets (slim records) ----------------
__global__ void __launch_bounds__(256) k_fill(const int* __restrict__ ei,
                                              const float* __restrict__ attr) {
    int e = blockIdx.x * 256 + threadIdx.x;
    if (e >= NE) return;
    int s = ei[e], dd = ei[NE + e];
    if ((unsigned)s >= NN || (unsigned)dd >= NN) return;
    int pos = atomicAdd(&d_cur[dd], 1);
    if ((unsigned)pos >= NE) return;
    d_sa[pos] = make_int2(s, __float_as_int(attr[e]));
    d_eid[pos] = e;
}

// ---------------- layer-1: single-pass softmax + rank-2 agg -> S, dots -----
__global__ void __launch_bounds__(256) k_agg1(const float* __restrict__ x) {
    int warp = threadIdx.x >> 5, lane = threadIdx.x & 31;
    int n = blockIdx.x * 8 + warp;   // grid exact
    int r0 = d_rs[n], r1 = d_rs[n + 1];

    float2 xn = __ldg((const float2*)x + n);
    float adh[4], u0[4], u1[4], c1[4];
#pragma unroll
    for (int h = 0; h < 4; h++) {
        u0[h] = d_u0[h]; u1[h] = d_u1[h]; c1[h] = d_c1[h];
        adh[h] = xn.x * d_v0[h] + xn.y * d_v1[h];
    }

    float z[4] = {0, 0, 0, 0};
    float acc[8] = {0, 0, 0, 0, 0, 0, 0, 0};
    for (int pos = r0 + lane; pos < r1; pos += 32) {
        int2 p = __ldg(&d_sa[pos]);
        float a = __int_as_float(p.y);
        float2 xs = __ldg((const float2*)x + p.x);
#pragma unroll
        for (int h = 0; h < 4; h++) {
            float lg = lrelu(xs.x * u0[h] + xs.y * u1[h] + adh[h] + a * c1[h]);
            float w = __expf(lg);
            z[h] += w;
            acc[2 * h] += w * xs.x;
            acc[2 * h + 1] += w * xs.y;
        }
    }
#pragma unroll
    for (int off = 16; off; off >>= 1) {
#pragma unroll
        for (int h = 0; h < 4; h++)
            z[h] += __shfl_xor_sync(0xffffffffu, z[h], off);
#pragma unroll
        for (int q = 0; q < 8; q++)
            acc[q] += __shfl_xor_sync(0xffffffffu, acc[q], off);
    }
    if (lane == 0) {
        float rz0 = 1.f / (z[0] + 1e-16f);
        float rz1 = 1.f / (z[1] + 1e-16f);
        float rz2 = 1.f / (z[2] + 1e-16f);
        float rz3 = 1.f / (z[3] + 1e-16f);
        float S0 = acc[0] * rz0, S1 = acc[2] * rz1, S2 = acc[4] * rz2, S3 = acc[6] * rz3;
        float S4 = acc[1] * rz0, S5 = acc[3] * rz1, S6 = acc[5] * rz2, S7 = acc[7] * rz3;
        float4* sp = (float4*)(d_S + (long)n * 8);
        sp[0] = make_float4(S0, S1, S2, S3);
        sp[1] = make_float4(S4, S5, S6, S7);
        d_als2[n] = d_cA + S0 * d_gA[0] + S1 * d_gA[1] + S2 * d_gA[2] + S3 * d_gA[3]
                         + S4 * d_gA[4] + S5 * d_gA[5] + S6 * d_gA[6] + S7 * d_gA[7];
        d_ald2[n] = d_cD + S0 * d_gD[0] + S1 * d_gD[1] + S2 * d_gD[2] + S3 * d_gD[3]
                         + S4 * d_gD[4] + S5 * d_gD[5] + S6 * d_gD[6] + S7 * d_gD[7];
    }
}

// ------- layer-2: softmax + rank-8 agg + fused gv epilogue (no T array) ----
__global__ void __launch_bounds__(256) k_agg2() {
    __shared__ float shGW[512];
    __shared__ float shB2[64], shBV[64];
    int t = threadIdx.x;
    shGW[t] = d_GW[t];
    shGW[256 + t] = d_GW[256 + t];
    if (t < 64) { shB2[t] = d_bB2[t]; shBV[t] = d_bBV[t]; }
    __syncthreads();

    int warp = t >> 5, lane = t & 31;
    int n = blockIdx.x * 8 + warp;   // grid exact
    int r0 = d_rs[n], r1 = d_rs[n + 1];
    float aldn = d_ald2[n];
    float c2 = d_c2s;

    float z = 0.f;
    float T[8] = {0, 0, 0, 0, 0, 0, 0, 0};
    for (int pos = r0 + lane; pos < r1; pos += 32) {
        int2 p = __ldg(&d_sa[pos]);
        float a = __int_as_float(p.y);
        float w = __expf(lrelu(__ldg(&d_als2[p.x]) + aldn + a * c2));
        const float4* sp = (const float4*)(d_S + (long)p.x * 8);
        float4 s0 = __ldg(sp), s1 = __ldg(sp + 1);
        z += w;
        T[0] += w * s0.x; T[1] += w * s0.y; T[2] += w * s0.z; T[3] += w * s0.w;
        T[4] += w * s1.x; T[5] += w * s1.y; T[6] += w * s1.z; T[7] += w * s1.w;
    }
#pragma unroll
    for (int off = 16; off; off >>= 1) {
        z += __shfl_xor_sync(0xffffffffu, z, off);
#pragma unroll
        for (int q = 0; q < 8; q++)
            T[q] += __shfl_xor_sync(0xffffffffu, T[q], off);
    }
    // after butterfly every lane holds full T and z
    float rz = 1.f / (z + 1e-16f);
    float s = (r1 > r0) ? 1.f : 0.f;
#pragma unroll
    for (int q = 0; q < 8; q++) T[q] *= rz;

    int c0 = lane * 2;
    float v0 = shB2[c0] + s * shBV[c0];
    float v1 = shB2[c0 + 1] + s * shBV[c0 + 1];
#pragma unroll
    for (int q = 0; q < 8; q++) {
        float2 g = *(const float2*)(shGW + q * 64 + c0);
        v0 += T[q] * g.x;
        v1 += T[q] * g.y;
    }
    *(float2*)(d_gv + (long)n * 64 + c0) = make_float2(v0, v1);
}

// ---------------- final edge regressor (warp per node; 4 edges parallel) ---
__global__ void __launch_bounds__(256) k_edge(const float* __restrict__ br1,
                                              const float* __restrict__ Wr2,
                                              const float* __restrict__ br2,
                                              float* __restrict__ out) {
    int warp = threadIdx.x >> 5, lane = threadIdx.x & 31;
    int n = blockIdx.x * 8 + warp;   // grid exact
    int r0 = d_rs[n], r1 = d_rs[n + 1];
    if (r0 >= r1) return;
    int g = lane >> 3;        // edge slot 0-3
    int l8 = lane & 7;        // dim octet
    int c0 = l8 * 8;
    const float4* gn = (const float4*)(d_gv + (long)n * 64 + c0);
    float4 b0 = gn[0], b1 = gn[1];
    float4 q0 = __ldg((const float4*)(br1 + c0)), q1 = __ldg((const float4*)(br1 + c0 + 4));
    b0.x += q0.x; b0.y += q0.y; b0.z += q0.z; b0.w += q0.w;
    b1.x += q1.x; b1.y += q1.y; b1.z += q1.z; b1.w += q1.w;
    float4 w0 = __ldg((const float4*)(Wr2 + c0)), w1 = __ldg((const float4*)(Wr2 + c0 + 4));
    float brv = __ldg(br2);

    for (int pos0 = r0; pos0 < r1; pos0 += 4) {
        int pos = pos0 + g;
        bool act = pos < r1;
        float p = 0.f;
        int eid = 0;
        if (act) {
            int s = __ldg(&d_sa[pos]).x;
            const float4* gs = (const float4*)(d_gv + (long)s * 64 + c0);
            float4 a0 = __ldg(gs), a1 = __ldg(gs + 1);
            p += fmaxf(a0.x + b0.x, 0.f) * w0.x;
            p += fmaxf(a0.y + b0.y, 0.f) * w0.y;
            p += fmaxf(a0.z + b0.z, 0.f) * w0.z;
            p += fmaxf(a0.w + b0.w, 0.f) * w0.w;
            p += fmaxf(a1.x + b1.x, 0.f) * w1.x;
            p += fmaxf(a1.y + b1.y, 0.f) * w1.y;
            p += fmaxf(a1.z + b1.z, 0.f) * w1.z;
            p += fmaxf(a1.w + b1.w, 0.f) * w1.w;
            eid = __ldg(&d_eid[pos]);
        }
#pragma unroll
        for (int off = 4; off; off >>= 1)
            p += __shfl_xor_sync(0xffffffffu, p, off);
        if (act && l8 == 0) out[eid] = p + brv;
    }
}

// ---------------- host diagnostics (static; no allocation) -----------------
static int   h_rs[1];
static float h_S[2], h_gv[2], h_out[8];

// ---------------- launch ----------------
extern "C" void kernel_launch(void* const* d_in, const int* in_sizes, int n_in,
                              void* d_out, int out_size) {
    const float* x    = (const float*)d_in[0];
    const int*   ei   = (const int*)d_in[1];
    const float* attr = (const float*)d_in[2];
    const float* W1   = (const float*)d_in[3];
    const float* We1  = (const float*)d_in[4];
    const float* as1  = (const float*)d_in[5];
    const float* ad1  = (const float*)d_in[6];
    const float* ae1  = (const float*)d_in[7];
    const float* b1   = (const float*)d_in[8];
    const float* W2   = (const float*)d_in[9];
    const float* We2  = (const float*)d_in[10];
    const float* as2  = (const float*)d_in[11];
    const float* ad2  = (const float*)d_in[12];
    const float* ae2  = (const float*)d_in[13];
    const float* b2   = (const float*)d_in[14];
    const float* Wr1  = (const float*)d_in[15];
    const float* br1  = (const float*)d_in[16];
    const float* Wr2  = (const float*)d_in[17];
    const float* br2  = (const float*)d_in[18];
    float* out = (float*)d_out;

    const int NB8 = (NN + 7) / 8;     // 12500 exact

    k_count_pre<<<EB + 1, 256>>>(ei, W1, as1, ad1, We1, ae1, We2, ae2,
                                 b1, W2, as2, ad2, b2, Wr1);
    k_scan1<<<SCB, 256>>>();
    k_scan3<<<SCB, 256>>>();
    k_fill<<<EB, 256>>>(ei, attr);
    k_agg1<<<NB8, 256>>>(x);
    k_agg2<<<NB8, 256>>>();
    k_edge<<<NB8, 256>>>(br1, Wr2, br2, out);

    // -------- slim health check: only on the non-capture correctness call --
    cudaStreamCaptureStatus cs = cudaStreamCaptureStatusNone;
    cudaStreamIsCapturing((cudaStream_t)0, &cs);
    if (cs != cudaStreamCaptureStatusNone) return;

    h_rs[0] = -777;
    cudaMemcpyFromSymbolAsync(h_rs, d_rs, 4, (size_t)NN * 4, cudaMemcpyDeviceToHost, 0);
    cudaMemcpyFromSymbolAsync(h_S, d_S, 8, 0, cudaMemcpyDeviceToHost, 0);
    cudaMemcpyFromSymbolAsync(h_gv, d_gv, 8, 0, cudaMemcpyDeviceToHost, 0);
    cudaMemcpyAsync(h_out, out, 32, cudaMemcpyDeviceToHost, 0);
    cudaError_t sticky = cudaGetLastError();

    float omax = 0.f;
    bool ofin = true;
    for (int i = 0; i < 8; i++) {
        if (!isfinite(h_out[i])) ofin = false;
        float a = fabsf(h_out[i]);
        if (a > omax) omax = a;
    }
    bool healthy = sticky == cudaSuccess && h_rs[0] == NE && ofin &&
                   omax > 1e-30f &&
                   (fabsf(h_gv[0]) + fabsf(h_gv[1])) > 0.f;
    if (healthy) return;

    for (int pass = 0; pass < 2; pass++) {
        FILE* f = pass ? stderr : stdout;
        fprintf(f, "DG sticky=%d(%s) rsN=%d S=[%g %g] gv=[%g %g] out=[%g %g %g %g]\n",
                (int)sticky, cudaGetErrorString(sticky), h_rs[0],
                h_S[0], h_S[1], h_gv[0], h_gv[1],
                h_out[0], h_out[1], h_out[2], h_out[3]);
        fflush(f);
    }
    abort();
}